// round 2
// baseline (speedup 1.0000x reference)
#include <cuda_runtime.h>
#include <math.h>

#define B_ 64
#define S_ 2048
#define D_ 512
#define A_ 256

// Scratch (allocation-free rule: __device__ globals)
__device__ float g_logits[B_ * S_];
__device__ float g_wts[B_ * S_];

// ---------------------------------------------------------------------------
// Kernel A: logits[b,s] = sum_a tanh( (x W)[bs,a] + b[a] ) * u[a]
// Register-tiled fp32 GEMM: 64 rows x 256 cols per block, K-chunks of 32.
// 256 threads, 8x8 accumulators per thread. Fused tanh+u epilogue with
// warp-shuffle reduction over the A dimension.
// ---------------------------------------------------------------------------
#define TM 64
#define TK 32

__global__ __launch_bounds__(256, 2) void logits_kernel(
    const float* __restrict__ x, const float* __restrict__ W,
    const float* __restrict__ bias, const float* __restrict__ u)
{
    __shared__ float xs[TK][TM + 1];   // +1 pad: conflict-free transposed store
    __shared__ float Ws[TK][A_];

    const int tid = threadIdx.x;
    const int tx = tid & 31;           // lane -> column group
    const int ty = tid >> 5;           // warp -> row group (8 rows/warp)
    const long row0 = (long)blockIdx.x * TM;

    float acc[8][8];
#pragma unroll
    for (int i = 0; i < 8; i++)
#pragma unroll
        for (int j = 0; j < 8; j++) acc[i][j] = 0.f;

    for (int k0 = 0; k0 < D_; k0 += TK) {
        // x tile: 64 rows x 32 k -> transposed into xs[k][row]
#pragma unroll
        for (int it = 0; it < 2; it++) {
            int idx = tid + 256 * it;          // 0..511
            int r  = idx >> 3;
            int kg = idx & 7;
            float4 v = *(const float4*)(x + (row0 + r) * D_ + k0 + kg * 4);
            xs[kg * 4 + 0][r] = v.x;
            xs[kg * 4 + 1][r] = v.y;
            xs[kg * 4 + 2][r] = v.z;
            xs[kg * 4 + 3][r] = v.w;
        }
        // W tile: 32 k x 256 cols (row-major, straight float4 copy)
#pragma unroll
        for (int it = 0; it < 8; it++) {
            int idx = tid + 256 * it;          // 0..2047
            int kk = idx >> 6;
            int cg = idx & 63;
            *(float4*)(&Ws[kk][cg * 4]) =
                *(const float4*)(W + (k0 + kk) * A_ + cg * 4);
        }
        __syncthreads();

#pragma unroll
        for (int kk = 0; kk < TK; kk++) {
            float a[8], bv[8];
#pragma unroll
            for (int i = 0; i < 8; i++) a[i] = xs[kk][ty * 8 + i];   // broadcast
#pragma unroll
            for (int j = 0; j < 8; j++) bv[j] = Ws[kk][tx + 32 * j]; // conflict-free
#pragma unroll
            for (int i = 0; i < 8; i++)
#pragma unroll
                for (int j = 0; j < 8; j++)
                    acc[i][j] = fmaf(a[i], bv[j], acc[i][j]);
        }
        __syncthreads();
    }

    // Epilogue: tanh, dot with u, warp-reduce over the 256 columns.
    float bb[8], uu[8];
#pragma unroll
    for (int j = 0; j < 8; j++) {
        int c = tx + 32 * j;
        bb[j] = bias[c];
        uu[j] = u[c];
    }
#pragma unroll
    for (int i = 0; i < 8; i++) {
        float part = 0.f;
#pragma unroll
        for (int j = 0; j < 8; j++)
            part += tanhf(acc[i][j] + bb[j]) * uu[j];
#pragma unroll
        for (int off = 16; off > 0; off >>= 1)
            part += __shfl_xor_sync(0xffffffffu, part, off);
        if (tx == 0) g_logits[row0 + ty * 8 + i] = part;
    }
}

// ---------------------------------------------------------------------------
// Kernel B: per-batch masked softmax over S (with keras EPS in denominator)
// NOTE: mask arrives as int32 (harness materializes JAX bool as int32).
// ---------------------------------------------------------------------------
__global__ __launch_bounds__(256) void softmax_kernel(
    const int* __restrict__ mask)
{
    const int b = blockIdx.x;
    const int tid = threadIdx.x;
    __shared__ float red[256];

    float local = 0.f;
    for (int s = tid; s < S_; s += 256) {
        float e = expf(g_logits[b * S_ + s]);
        e = (mask[b * S_ + s] != 0) ? e : 0.f;
        g_wts[b * S_ + s] = e;
        local += e;
    }
    red[tid] = local;
    __syncthreads();
#pragma unroll
    for (int off = 128; off > 0; off >>= 1) {
        if (tid < off) red[tid] += red[tid + off];
        __syncthreads();
    }
    const float inv = 1.f / (red[0] + 1e-7f);
    for (int s = tid; s < S_; s += 256)
        g_wts[b * S_ + s] *= inv;
}

// ---------------------------------------------------------------------------
// Kernel C0: zero the output (it arrives poisoned)
// ---------------------------------------------------------------------------
__global__ void zero_kernel(float* __restrict__ out)
{
    out[blockIdx.x * 512 + threadIdx.x] = 0.f;
}

// ---------------------------------------------------------------------------
// Kernel C: out[b,d] += sum_{s in chunk} x[b,s,d] * w[b,s]   (split-S, atomics)
// grid (64, 8), 512 threads (one column each), 256 s per block.
// ---------------------------------------------------------------------------
#define SCHUNK 256
__global__ __launch_bounds__(512) void wsum_kernel(
    const float* __restrict__ x, float* __restrict__ out)
{
    const int b = blockIdx.x;
    const int s0 = blockIdx.y * SCHUNK;
    const int d = threadIdx.x;

    __shared__ float wsh[SCHUNK];
    for (int i = threadIdx.x; i < SCHUNK; i += 512)
        wsh[i] = g_wts[b * S_ + s0 + i];
    __syncthreads();

    float acc = 0.f;
    const float* xp = x + ((long)b * S_ + s0) * D_ + d;
#pragma unroll 4
    for (int s = 0; s < SCHUNK; s++)
        acc = fmaf(xp[(long)s * D_], wsh[s], acc);

    atomicAdd(&out[b * D_ + d], acc);
}

// ---------------------------------------------------------------------------
extern "C" void kernel_launch(void* const* d_in, const int* in_sizes, int n_in,
                              void* d_out, int out_size)
{
    const float* x    = (const float*)d_in[0];
    const int*   mask = (const int*)d_in[1];   // JAX bool -> int32 in harness
    const float* W    = (const float*)d_in[2];
    const float* bias = (const float*)d_in[3];
    const float* u    = (const float*)d_in[4];
    float*       out  = (float*)d_out;

    logits_kernel<<<(B_ * S_) / TM, 256>>>(x, W, bias, u);
    softmax_kernel<<<B_, 256>>>(mask);
    zero_kernel<<<B_, 512>>>(out);
    wsum_kernel<<<dim3(B_, S_ / SCHUNK), 512>>>(x, out);
}

// round 4
// speedup vs baseline: 2.2875x; 2.2875x over previous
#include <cuda_runtime.h>
#include <cuda_bf16.h>
#include <math.h>
#include <stdint.h>

#define B_ 64
#define S_ 2048
#define D_ 512
#define A_ 256
#define BS_ (B_ * S_)

// Scratch (allocation-free rule: __device__ globals)
__device__ float g_logits[BS_];
__device__ float g_wts[BS_];
// W transposed + bf16-split: WT[a][d] (== col-major B for mma .row.col)
__device__ __nv_bfloat16 g_WTh[A_ * D_];
__device__ __nv_bfloat16 g_WTl[A_ * D_];

// ---------------------------------------------------------------------------
// helpers
// ---------------------------------------------------------------------------
__device__ __forceinline__ uint32_t smem_u32(const void* p) {
    uint32_t a;
    asm("{ .reg .u64 t; cvta.to.shared.u64 t, %1; cvt.u32.u64 %0, t; }"
        : "=r"(a) : "l"(p));
    return a;
}

__device__ __forceinline__ void ldsm_x4(uint32_t addr, uint32_t& r0, uint32_t& r1,
                                        uint32_t& r2, uint32_t& r3) {
    asm volatile("ldmatrix.sync.aligned.m8n8.x4.shared.b16 {%0,%1,%2,%3}, [%4];"
                 : "=r"(r0), "=r"(r1), "=r"(r2), "=r"(r3) : "r"(addr));
}

__device__ __forceinline__ void mma_bf16(float* d, const uint32_t* a,
                                         uint32_t b0, uint32_t b1) {
    asm volatile(
        "mma.sync.aligned.m16n8k16.row.col.f32.bf16.bf16.f32 "
        "{%0,%1,%2,%3}, {%4,%5,%6,%7}, {%8,%9}, {%0,%1,%2,%3};"
        : "+f"(d[0]), "+f"(d[1]), "+f"(d[2]), "+f"(d[3])
        : "r"(a[0]), "r"(a[1]), "r"(a[2]), "r"(a[3]), "r"(b0), "r"(b1));
}

__device__ __forceinline__ void cp16(uint32_t saddr, const void* gptr) {
    asm volatile("cp.async.cg.shared.global [%0], [%1], 16;"
                 :: "r"(saddr), "l"(gptr));
}
__device__ __forceinline__ void cp_commit() {
    asm volatile("cp.async.commit_group;" ::: "memory");
}
__device__ __forceinline__ void cp_wait0() {
    asm volatile("cp.async.wait_group 0;" ::: "memory");
}

__device__ __forceinline__ uint32_t pack_bf(float a, float b) {
    __nv_bfloat162 h = __floats2bfloat162_rn(a, b);
    return *(uint32_t*)&h;
}

// ---------------------------------------------------------------------------
// Kernel W-prep: WT_h[a][d] = bf16_hi(W[d][a]), WT_l = bf16(residual)
// ---------------------------------------------------------------------------
__global__ void wprep_kernel(const float* __restrict__ W) {
    int idx = blockIdx.x * 256 + threadIdx.x;   // 0..131071
    int d = idx >> 8, a = idx & 255;
    float w = W[d * A_ + a];
    __nv_bfloat16 h = __float2bfloat16(w);
    float l = w - __bfloat162float(h);
    g_WTh[a * D_ + d] = h;
    g_WTl[a * D_ + d] = __float2bfloat16(l);
}

// ---------------------------------------------------------------------------
// Kernel A: mma.sync bf16 3-split GEMM, 128 rows x 256 cols per CTA, K=512.
// 512 threads = 16 warps in 4(m) x 4(n); warp tile 32x64.
// SMEM rows padded to 80B -> conflict-free ldmatrix. W double-buffered cp.async.
// Fused tanh+u epilogue -> g_logits.
// ---------------------------------------------------------------------------
#define TKC 32
#define NCHUNK (D_ / TKC)           // 16
#define XROW 80                     // 32 bf16 = 64B, padded to 80
#define OFF_XH 0
#define OFF_XL (128 * XROW)                 // 10240
#define OFF_W  (2 * 128 * XROW)             // 20480
#define WBUF_BYTES (2 * 256 * XROW)         // 40960 (WH + WL)
#define OFF_RED (OFF_W + 2 * WBUF_BYTES)    // 102400
#define SMEM_BYTES (OFF_RED + 512)          // 102912

__global__ __launch_bounds__(512, 1) void logits_mma_kernel(
    const float* __restrict__ x, const float* __restrict__ bias,
    const float* __restrict__ u)
{
    extern __shared__ char smem[];
    const uint32_t sb = smem_u32(smem);
    float* sm_red = (float*)(smem + OFF_RED);

    const int tid  = threadIdx.x;
    const int wid  = tid >> 5;
    const int lane = tid & 31;
    const int warp_m = wid & 3;          // row group (32 rows)
    const int warp_n = wid >> 2;         // col group (64 cols)
    const long row0 = (long)blockIdx.x * 128;

    if (tid < 128) sm_red[tid] = 0.f;

    // x staging mapping: 4 threads per row, 8 floats each
    const int row_x = tid >> 2;
    const int kq_x  = (tid & 3) * 8;
    const float* gx = x + (row0 + row_x) * D_ + kq_x;

    // W cp.async mapping: 2 threads per row (n), 2x16B per split each
    const int n_w  = tid >> 1;
    const int half = tid & 1;
    const __nv_bfloat16* gwh = g_WTh + n_w * D_ + half * 16;
    const __nv_bfloat16* gwl = g_WTl + n_w * D_ + half * 16;
    const uint32_t wdst_row = n_w * XROW + half * 32;

    float acc[2][8][4];
#pragma unroll
    for (int i = 0; i < 2; i++)
#pragma unroll
        for (int j = 0; j < 8; j++)
#pragma unroll
            for (int k = 0; k < 4; k++) acc[i][j][k] = 0.f;

    // preload chunk 0
    float4 xv0 = *(const float4*)(gx);
    float4 xv1 = *(const float4*)(gx + 4);
    {
        uint32_t wb = sb + OFF_W;            // buffer 0
        cp16(wb + wdst_row,              gwh);
        cp16(wb + wdst_row + 16,         gwh + 8);
        cp16(wb + 20480 + wdst_row,      gwl);
        cp16(wb + 20480 + wdst_row + 16, gwl + 8);
        cp_commit();
    }

    // ldmatrix lane addressing (constant across chunks)
    const int a_row  = (lane & 15);
    const int a_kb   = (lane >> 4) * 16;
    const int t      = lane >> 3;
    const int b_noff = (lane & 7) + 8 * (t >> 1);
    const int b_kb   = 16 * (t & 1);

    for (int c = 0; c < NCHUNK; c++) {
        __syncthreads();   // previous chunk's mma done -> x smem reusable

        // split + store x chunk c
        {
            uint4 hi, lo;
            hi.x = pack_bf(xv0.x, xv0.y); hi.y = pack_bf(xv0.z, xv0.w);
            hi.z = pack_bf(xv1.x, xv1.y); hi.w = pack_bf(xv1.z, xv1.w);
            lo.x = pack_bf(xv0.x - __bfloat162float(__float2bfloat16(xv0.x)),
                           xv0.y - __bfloat162float(__float2bfloat16(xv0.y)));
            lo.y = pack_bf(xv0.z - __bfloat162float(__float2bfloat16(xv0.z)),
                           xv0.w - __bfloat162float(__float2bfloat16(xv0.w)));
            lo.z = pack_bf(xv1.x - __bfloat162float(__float2bfloat16(xv1.x)),
                           xv1.y - __bfloat162float(__float2bfloat16(xv1.y)));
            lo.w = pack_bf(xv1.z - __bfloat162float(__float2bfloat16(xv1.z)),
                           xv1.w - __bfloat162float(__float2bfloat16(xv1.w)));
            uint32_t off = row_x * XROW + kq_x * 2;
            *(uint4*)(smem + OFF_XH + off) = hi;
            *(uint4*)(smem + OFF_XL + off) = lo;
        }

        cp_wait0();        // W chunk c resident
        __syncthreads();

        // prefetch chunk c+1 (overlaps with mma below)
        if (c + 1 < NCHUNK) {
            xv0 = *(const float4*)(gx + (c + 1) * TKC);
            xv1 = *(const float4*)(gx + (c + 1) * TKC + 4);
            uint32_t wb = sb + OFF_W + ((c + 1) & 1) * WBUF_BYTES;
            const __nv_bfloat16* sh = gwh + (c + 1) * TKC;
            const __nv_bfloat16* sl = gwl + (c + 1) * TKC;
            cp16(wb + wdst_row,              sh);
            cp16(wb + wdst_row + 16,         sh + 8);
            cp16(wb + 20480 + wdst_row,      sl);
            cp16(wb + 20480 + wdst_row + 16, sl + 8);
            cp_commit();
        }

        const uint32_t xh = sb + OFF_XH;
        const uint32_t xl = sb + OFF_XL;
        const uint32_t wh = sb + OFF_W + (c & 1) * WBUF_BYTES;
        const uint32_t wl = wh + 20480;

#pragma unroll
        for (int ks = 0; ks < 2; ks++) {
            uint32_t ah[2][4], al[2][4];
#pragma unroll
            for (int mt = 0; mt < 2; mt++) {
                uint32_t ra = (warp_m * 32 + mt * 16 + a_row) * XROW + ks * 32 + a_kb;
                ldsm_x4(xh + ra, ah[mt][0], ah[mt][1], ah[mt][2], ah[mt][3]);
                ldsm_x4(xl + ra, al[mt][0], al[mt][1], al[mt][2], al[mt][3]);
            }
#pragma unroll
            for (int pair = 0; pair < 4; pair++) {
                uint32_t rb = (warp_n * 64 + pair * 16 + b_noff) * XROW + ks * 32 + b_kb;
                uint32_t bh0, bh1, bh2, bh3, bl0, bl1, bl2, bl3;
                ldsm_x4(wh + rb, bh0, bh1, bh2, bh3);
                ldsm_x4(wl + rb, bl0, bl1, bl2, bl3);
#pragma unroll
                for (int mt = 0; mt < 2; mt++) {
                    mma_bf16(acc[mt][pair * 2 + 0], ah[mt], bh0, bh1);
                    mma_bf16(acc[mt][pair * 2 + 1], ah[mt], bh2, bh3);
                    mma_bf16(acc[mt][pair * 2 + 0], ah[mt], bl0, bl1);
                    mma_bf16(acc[mt][pair * 2 + 1], ah[mt], bl2, bl3);
                    mma_bf16(acc[mt][pair * 2 + 0], al[mt], bh0, bh1);
                    mma_bf16(acc[mt][pair * 2 + 1], al[mt], bh2, bh3);
                }
            }
        }
    }

    // ---- epilogue: tanh(acc + bias) * u, reduce over 256 cols per row ----
#pragma unroll
    for (int mt = 0; mt < 2; mt++) {
        float r0acc = 0.f, r1acc = 0.f;
#pragma unroll
        for (int j = 0; j < 8; j++) {
            int col = warp_n * 64 + j * 8 + 2 * (lane & 3);
            float b0 = bias[col], b1 = bias[col + 1];
            float u0 = u[col],    u1 = u[col + 1];
            r0acc += tanhf(acc[mt][j][0] + b0) * u0 + tanhf(acc[mt][j][1] + b1) * u1;
            r1acc += tanhf(acc[mt][j][2] + b0) * u0 + tanhf(acc[mt][j][3] + b1) * u1;
        }
        r0acc += __shfl_xor_sync(0xffffffffu, r0acc, 1);
        r0acc += __shfl_xor_sync(0xffffffffu, r0acc, 2);
        r1acc += __shfl_xor_sync(0xffffffffu, r1acc, 1);
        r1acc += __shfl_xor_sync(0xffffffffu, r1acc, 2);
        if ((lane & 3) == 0) {
            int lrow = warp_m * 32 + mt * 16 + (lane >> 2);
            atomicAdd(&sm_red[lrow],     r0acc);
            atomicAdd(&sm_red[lrow + 8], r1acc);
        }
    }
    __syncthreads();
    if (tid < 128) g_logits[row0 + tid] = sm_red[tid];
}

// ---------------------------------------------------------------------------
// Kernel B: per-batch masked softmax over S (mask is int32 from harness)
// ---------------------------------------------------------------------------
__global__ __launch_bounds__(256) void softmax_kernel(const int* __restrict__ mask)
{
    const int b = blockIdx.x;
    const int tid = threadIdx.x;
    __shared__ float red[256];

    float local = 0.f;
    for (int s = tid; s < S_; s += 256) {
        float e = expf(g_logits[b * S_ + s]);
        e = (mask[b * S_ + s] != 0) ? e : 0.f;
        g_wts[b * S_ + s] = e;
        local += e;
    }
    red[tid] = local;
    __syncthreads();
#pragma unroll
    for (int off = 128; off > 0; off >>= 1) {
        if (tid < off) red[tid] += red[tid + off];
        __syncthreads();
    }
    const float inv = 1.f / (red[0] + 1e-7f);
    for (int s = tid; s < S_; s += 256)
        g_wts[b * S_ + s] *= inv;
}

__global__ void zero_kernel(float* __restrict__ out)
{
    out[blockIdx.x * 512 + threadIdx.x] = 0.f;
}

// ---------------------------------------------------------------------------
// Kernel C: out[b,d] += sum_{s chunk} x[b,s,d] * w[b,s]
// ---------------------------------------------------------------------------
#define SCHUNK 256
__global__ __launch_bounds__(512) void wsum_kernel(
    const float* __restrict__ x, float* __restrict__ out)
{
    const int b = blockIdx.x;
    const int s0 = blockIdx.y * SCHUNK;
    const int d = threadIdx.x;

    __shared__ float wsh[SCHUNK];
    for (int i = threadIdx.x; i < SCHUNK; i += 512)
        wsh[i] = g_wts[b * S_ + s0 + i];
    __syncthreads();

    float acc = 0.f;
    const float* xp = x + ((long)b * S_ + s0) * D_ + d;
#pragma unroll 4
    for (int s = 0; s < SCHUNK; s++)
        acc = fmaf(xp[(long)s * D_], wsh[s], acc);

    atomicAdd(&out[b * D_ + d], acc);
}

// ---------------------------------------------------------------------------
extern "C" void kernel_launch(void* const* d_in, const int* in_sizes, int n_in,
                              void* d_out, int out_size)
{
    const float* x    = (const float*)d_in[0];
    const int*   mask = (const int*)d_in[1];
    const float* W    = (const float*)d_in[2];
    const float* bias = (const float*)d_in[3];
    const float* u    = (const float*)d_in[4];
    float*       out  = (float*)d_out;

    cudaFuncSetAttribute(logits_mma_kernel,
                         cudaFuncAttributeMaxDynamicSharedMemorySize, SMEM_BYTES);

    wprep_kernel<<<512, 256>>>(W);
    logits_mma_kernel<<<BS_ / 128, 512, SMEM_BYTES>>>(x, bias, u);
    softmax_kernel<<<B_, 256>>>(mask);
    zero_kernel<<<B_, 512>>>(out);
    wsum_kernel<<<dim3(B_, S_ / SCHUNK), 512>>>(x, out);
}

// round 5
// speedup vs baseline: 2.3166x; 1.0128x over previous
#include <cuda_runtime.h>
#include <cuda_bf16.h>
#include <math.h>
#include <stdint.h>

#define B_ 64
#define S_ 2048
#define D_ 512
#define A_ 256
#define BS_ (B_ * S_)

// Scratch (allocation-free rule: __device__ globals)
__device__ float g_logits[BS_];
__device__ float g_wts[BS_];
// W transposed + bf16-split: WT[a][d] (== col-major B for mma .row.col)
__device__ __nv_bfloat16 g_WTh[A_ * D_];
__device__ __nv_bfloat16 g_WTl[A_ * D_];

// ---------------------------------------------------------------------------
// helpers
// ---------------------------------------------------------------------------
__device__ __forceinline__ uint32_t smem_u32(const void* p) {
    uint32_t a;
    asm("{ .reg .u64 t; cvta.to.shared.u64 t, %1; cvt.u32.u64 %0, t; }"
        : "=r"(a) : "l"(p));
    return a;
}

__device__ __forceinline__ void ldsm_x4(uint32_t addr, uint32_t& r0, uint32_t& r1,
                                        uint32_t& r2, uint32_t& r3) {
    asm volatile("ldmatrix.sync.aligned.m8n8.x4.shared.b16 {%0,%1,%2,%3}, [%4];"
                 : "=r"(r0), "=r"(r1), "=r"(r2), "=r"(r3) : "r"(addr));
}

__device__ __forceinline__ void mma_bf16(float* d, const uint32_t* a,
                                         uint32_t b0, uint32_t b1) {
    asm volatile(
        "mma.sync.aligned.m16n8k16.row.col.f32.bf16.bf16.f32 "
        "{%0,%1,%2,%3}, {%4,%5,%6,%7}, {%8,%9}, {%0,%1,%2,%3};"
        : "+f"(d[0]), "+f"(d[1]), "+f"(d[2]), "+f"(d[3])
        : "r"(a[0]), "r"(a[1]), "r"(a[2]), "r"(a[3]), "r"(b0), "r"(b1));
}

__device__ __forceinline__ void cp16(uint32_t saddr, const void* gptr) {
    asm volatile("cp.async.cg.shared.global [%0], [%1], 16;"
                 :: "r"(saddr), "l"(gptr));
}
__device__ __forceinline__ void cp_commit() {
    asm volatile("cp.async.commit_group;" ::: "memory");
}
__device__ __forceinline__ void cp_wait0() {
    asm volatile("cp.async.wait_group 0;" ::: "memory");
}

__device__ __forceinline__ uint32_t pack_bf(float a, float b) {
    __nv_bfloat162 h = __floats2bfloat162_rn(a, b);
    return *(uint32_t*)&h;
}

// tanh via ex2/rcp MUFU path: err ~1e-6, ~5 instr vs ~30 for libdevice tanhf
__device__ __forceinline__ float tanh_fast(float x) {
    float e = __expf(2.f * x);
    return 1.f - __fdividef(2.f, e + 1.f);
}

// ---------------------------------------------------------------------------
// Kernel W-prep: WT_h[a][d] = bf16_hi(W[d][a]), WT_l = bf16(residual)
// ---------------------------------------------------------------------------
__global__ void wprep_kernel(const float* __restrict__ W) {
    int idx = blockIdx.x * 256 + threadIdx.x;   // 0..131071
    int d = idx >> 8, a = idx & 255;
    float w = W[d * A_ + a];
    __nv_bfloat16 h = __float2bfloat16(w);
    float l = w - __bfloat162float(h);
    g_WTh[a * D_ + d] = h;
    g_WTl[a * D_ + d] = __float2bfloat16(l);
}

// ---------------------------------------------------------------------------
// Kernel A: mma.sync bf16 3-split GEMM, 128 rows x 256 cols per CTA, K=512.
// 512 threads = 16 warps in 4(m) x 4(n); warp tile 32x64.
// SMEM rows padded to 80B -> conflict-free ldmatrix.
// BOTH x and W double-buffered: ONE __syncthreads + ONE cp.async wait per chunk;
// x-split stores and next-chunk cp.async overlap the current chunk's MMA.
// Fused tanh+u epilogue -> g_logits.
// ---------------------------------------------------------------------------
#define TKC 32
#define NCHUNK (D_ / TKC)           // 16
#define XROW 80                     // 32 bf16 = 64B, padded to 80
#define XBUF (128 * XROW)                   // 10240 per split per stage
#define OFF_XH 0                            // [2 stages][128*80]
#define OFF_XL (2 * XBUF)                   // 20480
#define OFF_W  (4 * XBUF)                   // 40960, [2 stages][WH|WL]
#define WHALF (256 * XROW)                  // 20480
#define WBUF_BYTES (2 * WHALF)              // 40960 per stage
#define OFF_RED (OFF_W + 2 * WBUF_BYTES)    // 122880
#define SMEM_BYTES (OFF_RED + 512)          // 123392

__global__ __launch_bounds__(512, 1) void logits_mma_kernel(
    const float* __restrict__ x, const float* __restrict__ bias,
    const float* __restrict__ u)
{
    extern __shared__ char smem[];
    const uint32_t sb = smem_u32(smem);
    float* sm_red = (float*)(smem + OFF_RED);

    const int tid  = threadIdx.x;
    const int wid  = tid >> 5;
    const int lane = tid & 31;
    const int warp_m = wid & 3;          // row group (32 rows)
    const int warp_n = wid >> 2;         // col group (64 cols)
    const long row0 = (long)blockIdx.x * 128;

    if (tid < 128) sm_red[tid] = 0.f;

    // x staging mapping: 4 threads per row, 8 floats each
    const int row_x = tid >> 2;
    const int kq_x  = (tid & 3) * 8;
    const float* gx = x + (row0 + row_x) * D_ + kq_x;
    const uint32_t xoff = (uint32_t)(row_x * XROW + kq_x * 2);

    // W cp.async mapping: 2 threads per row (n), 2x16B per split each
    const int n_w  = tid >> 1;
    const int half = tid & 1;
    const __nv_bfloat16* gwh = g_WTh + n_w * D_ + half * 16;
    const __nv_bfloat16* gwl = g_WTl + n_w * D_ + half * 16;
    const uint32_t wdst_row = n_w * XROW + half * 32;

    float acc[2][8][4];
#pragma unroll
    for (int i = 0; i < 2; i++)
#pragma unroll
        for (int j = 0; j < 8; j++)
#pragma unroll
            for (int k = 0; k < 4; k++) acc[i][j][k] = 0.f;

    // ---- preload chunk 0: x split into stage 0, W cp.async stage 0 ----
    {
        float4 v0 = *(const float4*)(gx);
        float4 v1 = *(const float4*)(gx + 4);
        uint4 hi, lo;
        hi.x = pack_bf(v0.x, v0.y); hi.y = pack_bf(v0.z, v0.w);
        hi.z = pack_bf(v1.x, v1.y); hi.w = pack_bf(v1.z, v1.w);
        lo.x = pack_bf(v0.x - __bfloat162float(__float2bfloat16(v0.x)),
                       v0.y - __bfloat162float(__float2bfloat16(v0.y)));
        lo.y = pack_bf(v0.z - __bfloat162float(__float2bfloat16(v0.z)),
                       v0.w - __bfloat162float(__float2bfloat16(v0.w)));
        lo.z = pack_bf(v1.x - __bfloat162float(__float2bfloat16(v1.x)),
                       v1.y - __bfloat162float(__float2bfloat16(v1.y)));
        lo.w = pack_bf(v1.z - __bfloat162float(__float2bfloat16(v1.z)),
                       v1.w - __bfloat162float(__float2bfloat16(v1.w)));
        *(uint4*)(smem + OFF_XH + xoff) = hi;
        *(uint4*)(smem + OFF_XL + xoff) = lo;

        uint32_t wb = sb + OFF_W;
        cp16(wb + wdst_row,                 gwh);
        cp16(wb + wdst_row + 16,            gwh + 8);
        cp16(wb + WHALF + wdst_row,         gwl);
        cp16(wb + WHALF + wdst_row + 16,    gwl + 8);
        cp_commit();
    }

    // ldmatrix lane addressing (constant across chunks)
    const int a_row  = (lane & 15);
    const int a_kb   = (lane >> 4) * 16;
    const int t      = lane >> 3;
    const int b_noff = (lane & 7) + 8 * (t >> 1);
    const int b_kb   = 16 * (t & 1);

    for (int c = 0; c < NCHUNK; c++) {
        const int st  = c & 1;
        const int stn = (c + 1) & 1;

        cp_wait0();          // W chunk c resident (only group in flight)
        __syncthreads();     // x chunk c stores visible; stage stn free to write

        // kick off W chunk c+1 (async, overlaps mma below)
        if (c + 1 < NCHUNK) {
            uint32_t wb = sb + OFF_W + stn * WBUF_BYTES;
            const __nv_bfloat16* sh = gwh + (c + 1) * TKC;
            const __nv_bfloat16* sl = gwl + (c + 1) * TKC;
            cp16(wb + wdst_row,              sh);
            cp16(wb + wdst_row + 16,         sh + 8);
            cp16(wb + WHALF + wdst_row,      sl);
            cp16(wb + WHALF + wdst_row + 16, sl + 8);
            cp_commit();
        }
        // x chunk c+1 global loads (in flight during mma)
        float4 xv0, xv1;
        if (c + 1 < NCHUNK) {
            xv0 = *(const float4*)(gx + (c + 1) * TKC);
            xv1 = *(const float4*)(gx + (c + 1) * TKC + 4);
        }

        const uint32_t xh = sb + OFF_XH + st * XBUF;
        const uint32_t xl = sb + OFF_XL + st * XBUF;
        const uint32_t wh = sb + OFF_W + st * WBUF_BYTES;
        const uint32_t wl = wh + WHALF;

#pragma unroll
        for (int ks = 0; ks < 2; ks++) {
            uint32_t ah[2][4], al[2][4];
#pragma unroll
            for (int mt = 0; mt < 2; mt++) {
                uint32_t ra = (warp_m * 32 + mt * 16 + a_row) * XROW + ks * 32 + a_kb;
                ldsm_x4(xh + ra, ah[mt][0], ah[mt][1], ah[mt][2], ah[mt][3]);
                ldsm_x4(xl + ra, al[mt][0], al[mt][1], al[mt][2], al[mt][3]);
            }
#pragma unroll
            for (int pair = 0; pair < 4; pair++) {
                uint32_t rb = (warp_n * 64 + pair * 16 + b_noff) * XROW + ks * 32 + b_kb;
                uint32_t bh0, bh1, bh2, bh3, bl0, bl1, bl2, bl3;
                ldsm_x4(wh + rb, bh0, bh1, bh2, bh3);
                ldsm_x4(wl + rb, bl0, bl1, bl2, bl3);
#pragma unroll
                for (int mt = 0; mt < 2; mt++) {
                    mma_bf16(acc[mt][pair * 2 + 0], ah[mt], bh0, bh1);
                    mma_bf16(acc[mt][pair * 2 + 1], ah[mt], bh2, bh3);
                    mma_bf16(acc[mt][pair * 2 + 0], ah[mt], bl0, bl1);
                    mma_bf16(acc[mt][pair * 2 + 1], ah[mt], bl2, bl3);
                    mma_bf16(acc[mt][pair * 2 + 0], al[mt], bh0, bh1);
                    mma_bf16(acc[mt][pair * 2 + 1], al[mt], bh2, bh3);
                }
            }
        }

        // split + store x chunk c+1 into stage stn (overlaps tail of mma;
        // readers of stage stn finished in chunk c-1, fenced by this chunk's bar)
        if (c + 1 < NCHUNK) {
            uint4 hi, lo;
            hi.x = pack_bf(xv0.x, xv0.y); hi.y = pack_bf(xv0.z, xv0.w);
            hi.z = pack_bf(xv1.x, xv1.y); hi.w = pack_bf(xv1.z, xv1.w);
            lo.x = pack_bf(xv0.x - __bfloat162float(__float2bfloat16(xv0.x)),
                           xv0.y - __bfloat162float(__float2bfloat16(xv0.y)));
            lo.y = pack_bf(xv0.z - __bfloat162float(__float2bfloat16(xv0.z)),
                           xv0.w - __bfloat162float(__float2bfloat16(xv0.w)));
            lo.z = pack_bf(xv1.x - __bfloat162float(__float2bfloat16(xv1.x)),
                           xv1.y - __bfloat162float(__float2bfloat16(xv1.y)));
            lo.w = pack_bf(xv1.z - __bfloat162float(__float2bfloat16(xv1.z)),
                           xv1.w - __bfloat162float(__float2bfloat16(xv1.w)));
            *(uint4*)(smem + OFF_XH + stn * XBUF + xoff) = hi;
            *(uint4*)(smem + OFF_XL + stn * XBUF + xoff) = lo;
        }
    }

    // ---- epilogue: tanh(acc + bias) * u, reduce over 256 cols per row ----
#pragma unroll
    for (int mt = 0; mt < 2; mt++) {
        float r0acc = 0.f, r1acc = 0.f;
#pragma unroll
        for (int j = 0; j < 8; j++) {
            int col = warp_n * 64 + j * 8 + 2 * (lane & 3);
            float b0 = bias[col], b1 = bias[col + 1];
            float u0 = u[col],    u1 = u[col + 1];
            r0acc += tanh_fast(acc[mt][j][0] + b0) * u0
                   + tanh_fast(acc[mt][j][1] + b1) * u1;
            r1acc += tanh_fast(acc[mt][j][2] + b0) * u0
                   + tanh_fast(acc[mt][j][3] + b1) * u1;
        }
        r0acc += __shfl_xor_sync(0xffffffffu, r0acc, 1);
        r0acc += __shfl_xor_sync(0xffffffffu, r0acc, 2);
        r1acc += __shfl_xor_sync(0xffffffffu, r1acc, 1);
        r1acc += __shfl_xor_sync(0xffffffffu, r1acc, 2);
        if ((lane & 3) == 0) {
            int lrow = warp_m * 32 + mt * 16 + (lane >> 2);
            atomicAdd(&sm_red[lrow],     r0acc);
            atomicAdd(&sm_red[lrow + 8], r1acc);
        }
    }
    __syncthreads();
    if (tid < 128) g_logits[row0 + tid] = sm_red[tid];
}

// ---------------------------------------------------------------------------
// Kernel B: per-batch masked softmax over S (mask is int32 from harness).
// Also zeroes this batch's 512 output floats (wsum accumulates atomically).
// ---------------------------------------------------------------------------
__global__ __launch_bounds__(256) void softmax_kernel(
    const int* __restrict__ mask, float* __restrict__ out)
{
    const int b = blockIdx.x;
    const int tid = threadIdx.x;
    __shared__ float red[256];

    out[b * 512 + tid] = 0.f;
    out[b * 512 + 256 + tid] = 0.f;

    float local = 0.f;
    for (int s = tid; s < S_; s += 256) {
        float e = expf(g_logits[b * S_ + s]);
        e = (mask[b * S_ + s] != 0) ? e : 0.f;
        g_wts[b * S_ + s] = e;
        local += e;
    }
    red[tid] = local;
    __syncthreads();
#pragma unroll
    for (int off = 128; off > 0; off >>= 1) {
        if (tid < off) red[tid] += red[tid + off];
        __syncthreads();
    }
    const float inv = 1.f / (red[0] + 1e-7f);
    for (int s = tid; s < S_; s += 256)
        g_wts[b * S_ + s] *= inv;
}

// ---------------------------------------------------------------------------
// Kernel C: out[b,d] += sum_{s chunk} x[b,s,d] * w[b,s]
// ---------------------------------------------------------------------------
#define SCHUNK 256
__global__ __launch_bounds__(512) void wsum_kernel(
    const float* __restrict__ x, float* __restrict__ out)
{
    const int b = blockIdx.x;
    const int s0 = blockIdx.y * SCHUNK;
    const int d = threadIdx.x;

    __shared__ float wsh[SCHUNK];
    for (int i = threadIdx.x; i < SCHUNK; i += 512)
        wsh[i] = g_wts[b * S_ + s0 + i];
    __syncthreads();

    float acc = 0.f;
    const float* xp = x + ((long)b * S_ + s0) * D_ + d;
#pragma unroll 4
    for (int s = 0; s < SCHUNK; s++)
        acc = fmaf(xp[(long)s * D_], wsh[s], acc);

    atomicAdd(&out[b * D_ + d], acc);
}

// ---------------------------------------------------------------------------
extern "C" void kernel_launch(void* const* d_in, const int* in_sizes, int n_in,
                              void* d_out, int out_size)
{
    const float* x    = (const float*)d_in[0];
    const int*   mask = (const int*)d_in[1];
    const float* W    = (const float*)d_in[2];
    const float* bias = (const float*)d_in[3];
    const float* u    = (const float*)d_in[4];
    float*       out  = (float*)d_out;

    cudaFuncSetAttribute(logits_mma_kernel,
                         cudaFuncAttributeMaxDynamicSharedMemorySize, SMEM_BYTES);

    wprep_kernel<<<512, 256>>>(W);
    logits_mma_kernel<<<BS_ / 128, 512, SMEM_BYTES>>>(x, bias, u);
    softmax_kernel<<<B_, 256>>>(mask, out);
    wsum_kernel<<<dim3(B_, S_ / SCHUNK), 512>>>(x, out);
}

// round 6
// speedup vs baseline: 3.0385x; 1.3116x over previous
#include <cuda_runtime.h>
#include <cuda_bf16.h>
#include <cuda_fp16.h>
#include <math.h>
#include <stdint.h>

#define B_ 64
#define S_ 2048
#define D_ 512
#define A_ 256
#define BS_ (B_ * S_)

// Scratch (allocation-free rule: __device__ globals)
__device__ float g_logits[BS_];
__device__ float g_wts[BS_];
// W transposed + fp16-split: WT[a][d] (== col-major B for mma .row.col)
__device__ __half g_WTh[A_ * D_];
__device__ __half g_WTl[A_ * D_];

// ---------------------------------------------------------------------------
// helpers
// ---------------------------------------------------------------------------
__device__ __forceinline__ uint32_t smem_u32(const void* p) {
    uint32_t a;
    asm("{ .reg .u64 t; cvta.to.shared.u64 t, %1; cvt.u32.u64 %0, t; }"
        : "=r"(a) : "l"(p));
    return a;
}

__device__ __forceinline__ void ldsm_x4(uint32_t addr, uint32_t& r0, uint32_t& r1,
                                        uint32_t& r2, uint32_t& r3) {
    asm volatile("ldmatrix.sync.aligned.m8n8.x4.shared.b16 {%0,%1,%2,%3}, [%4];"
                 : "=r"(r0), "=r"(r1), "=r"(r2), "=r"(r3) : "r"(addr));
}

__device__ __forceinline__ void mma_f16(float* d, const uint32_t* a,
                                        uint32_t b0, uint32_t b1) {
    asm volatile(
        "mma.sync.aligned.m16n8k16.row.col.f32.f16.f16.f32 "
        "{%0,%1,%2,%3}, {%4,%5,%6,%7}, {%8,%9}, {%0,%1,%2,%3};"
        : "+f"(d[0]), "+f"(d[1]), "+f"(d[2]), "+f"(d[3])
        : "r"(a[0]), "r"(a[1]), "r"(a[2]), "r"(a[3]), "r"(b0), "r"(b1));
}

__device__ __forceinline__ void cp16(uint32_t saddr, const void* gptr) {
    asm volatile("cp.async.cg.shared.global [%0], [%1], 16;"
                 :: "r"(saddr), "l"(gptr));
}
__device__ __forceinline__ void cp_commit() {
    asm volatile("cp.async.commit_group;" ::: "memory");
}
__device__ __forceinline__ void cp_wait0() {
    asm volatile("cp.async.wait_group 0;" ::: "memory");
}

__device__ __forceinline__ uint32_t pack_h2(float a, float b) {
    __half2 h = __floats2half2_rn(a, b);
    return *(uint32_t*)&h;
}

// tanh via ex2/rcp MUFU path: err ~1e-6
__device__ __forceinline__ float tanh_fast(float x) {
    float e = __expf(2.f * x);
    return 1.f - __fdividef(2.f, e + 1.f);
}

// ---------------------------------------------------------------------------
// Kernel W-prep: WT_h[a][d] = fp16(W[d][a]), WT_l = fp16(residual)
// ---------------------------------------------------------------------------
__global__ void wprep_kernel(const float* __restrict__ W) {
    int idx = blockIdx.x * 256 + threadIdx.x;   // 0..131071
    int d = idx >> 8, a = idx & 255;
    float w = W[d * A_ + a];
    __half h = __float2half_rn(w);
    float l = w - __half2float(h);
    g_WTh[a * D_ + d] = h;
    g_WTl[a * D_ + d] = __float2half_rn(l);
}

// ---------------------------------------------------------------------------
// Kernel A: mma.sync fp16 2-term GEMM, 128 rows x 256 cols per CTA, K=512.
// D = xh*(Wh + Wl): x in fp16 (err 2^-12 absorbed), W in fp16-split (22 bit).
// 512 threads = 16 warps in 4(m) x 4(n); warp tile 32x64.
// SMEM rows padded to 80B -> conflict-free ldmatrix.
// x (1 split) + W (2 splits) double-buffered; one barrier per chunk.
// Fused tanh+u epilogue -> g_logits.
// ---------------------------------------------------------------------------
#define TKC 32
#define NCHUNK (D_ / TKC)           // 16
#define XROW 80                     // 32 fp16 = 64B, padded to 80
#define XBUF (128 * XROW)                   // 10240 per stage
#define OFF_XH 0                            // [2 stages]
#define OFF_W  (2 * XBUF)                   // 20480, [2 stages][WH|WL]
#define WHALF (256 * XROW)                  // 20480
#define WBUF_BYTES (2 * WHALF)              // 40960 per stage
#define OFF_RED (OFF_W + 2 * WBUF_BYTES)    // 102400
#define SMEM_BYTES (OFF_RED + 512)          // 102912

__global__ __launch_bounds__(512, 1) void logits_mma_kernel(
    const float* __restrict__ x, const float* __restrict__ bias,
    const float* __restrict__ u)
{
    extern __shared__ char smem[];
    const uint32_t sb = smem_u32(smem);
    float* sm_red = (float*)(smem + OFF_RED);

    const int tid  = threadIdx.x;
    const int wid  = tid >> 5;
    const int lane = tid & 31;
    const int warp_m = wid & 3;          // row group (32 rows)
    const int warp_n = wid >> 2;         // col group (64 cols)
    const long row0 = (long)blockIdx.x * 128;

    if (tid < 128) sm_red[tid] = 0.f;

    // x staging mapping: 4 threads per row, 8 floats each
    const int row_x = tid >> 2;
    const int kq_x  = (tid & 3) * 8;
    const float* gx = x + (row0 + row_x) * D_ + kq_x;
    const uint32_t xoff = (uint32_t)(row_x * XROW + kq_x * 2);

    // W cp.async mapping: 2 threads per row (n), 2x16B per split each
    const int n_w  = tid >> 1;
    const int half = tid & 1;
    const __half* gwh = g_WTh + n_w * D_ + half * 16;
    const __half* gwl = g_WTl + n_w * D_ + half * 16;
    const uint32_t wdst_row = n_w * XROW + half * 32;

    float acc[2][8][4];
#pragma unroll
    for (int i = 0; i < 2; i++)
#pragma unroll
        for (int j = 0; j < 8; j++)
#pragma unroll
            for (int k = 0; k < 4; k++) acc[i][j][k] = 0.f;

    // ---- preload chunk 0 ----
    {
        float4 v0 = *(const float4*)(gx);
        float4 v1 = *(const float4*)(gx + 4);
        uint4 hi;
        hi.x = pack_h2(v0.x, v0.y); hi.y = pack_h2(v0.z, v0.w);
        hi.z = pack_h2(v1.x, v1.y); hi.w = pack_h2(v1.z, v1.w);
        *(uint4*)(smem + OFF_XH + xoff) = hi;

        uint32_t wb = sb + OFF_W;
        cp16(wb + wdst_row,              gwh);
        cp16(wb + wdst_row + 16,         gwh + 8);
        cp16(wb + WHALF + wdst_row,      gwl);
        cp16(wb + WHALF + wdst_row + 16, gwl + 8);
        cp_commit();
    }

    // ldmatrix lane addressing (constant across chunks)
    const int a_row  = (lane & 15);
    const int a_kb   = (lane >> 4) * 16;
    const int t      = lane >> 3;
    const int b_noff = (lane & 7) + 8 * (t >> 1);
    const int b_kb   = 16 * (t & 1);

    for (int c = 0; c < NCHUNK; c++) {
        const int st  = c & 1;
        const int stn = (c + 1) & 1;

        cp_wait0();          // W chunk c resident
        __syncthreads();     // x chunk c stores visible; stage stn free

        // kick off W chunk c+1 (async, overlaps mma)
        if (c + 1 < NCHUNK) {
            uint32_t wb = sb + OFF_W + stn * WBUF_BYTES;
            const __half* sh = gwh + (c + 1) * TKC;
            const __half* sl = gwl + (c + 1) * TKC;
            cp16(wb + wdst_row,              sh);
            cp16(wb + wdst_row + 16,         sh + 8);
            cp16(wb + WHALF + wdst_row,      sl);
            cp16(wb + WHALF + wdst_row + 16, sl + 8);
            cp_commit();
        }
        // x chunk c+1 global loads (in flight during mma)
        float4 xv0, xv1;
        if (c + 1 < NCHUNK) {
            xv0 = *(const float4*)(gx + (c + 1) * TKC);
            xv1 = *(const float4*)(gx + (c + 1) * TKC + 4);
        }

        const uint32_t xh = sb + OFF_XH + st * XBUF;
        const uint32_t wh = sb + OFF_W + st * WBUF_BYTES;
        const uint32_t wl = wh + WHALF;

#pragma unroll
        for (int ks = 0; ks < 2; ks++) {
            uint32_t ah[2][4];
#pragma unroll
            for (int mt = 0; mt < 2; mt++) {
                uint32_t ra = (warp_m * 32 + mt * 16 + a_row) * XROW + ks * 32 + a_kb;
                ldsm_x4(xh + ra, ah[mt][0], ah[mt][1], ah[mt][2], ah[mt][3]);
            }
#pragma unroll
            for (int pair = 0; pair < 4; pair++) {
                uint32_t rb = (warp_n * 64 + pair * 16 + b_noff) * XROW + ks * 32 + b_kb;
                uint32_t bh0, bh1, bh2, bh3, bl0, bl1, bl2, bl3;
                ldsm_x4(wh + rb, bh0, bh1, bh2, bh3);
                ldsm_x4(wl + rb, bl0, bl1, bl2, bl3);
#pragma unroll
                for (int mt = 0; mt < 2; mt++) {
                    mma_f16(acc[mt][pair * 2 + 0], ah[mt], bh0, bh1);
                    mma_f16(acc[mt][pair * 2 + 1], ah[mt], bh2, bh3);
                    mma_f16(acc[mt][pair * 2 + 0], ah[mt], bl0, bl1);
                    mma_f16(acc[mt][pair * 2 + 1], ah[mt], bl2, bl3);
                }
            }
        }

        // store x chunk c+1 into stage stn (readers finished chunk c-1)
        if (c + 1 < NCHUNK) {
            uint4 hi;
            hi.x = pack_h2(xv0.x, xv0.y); hi.y = pack_h2(xv0.z, xv0.w);
            hi.z = pack_h2(xv1.x, xv1.y); hi.w = pack_h2(xv1.z, xv1.w);
            *(uint4*)(smem + OFF_XH + stn * XBUF + xoff) = hi;
        }
    }

    // ---- epilogue: tanh(acc + bias) * u, reduce over 256 cols per row ----
#pragma unroll
    for (int mt = 0; mt < 2; mt++) {
        float r0acc = 0.f, r1acc = 0.f;
#pragma unroll
        for (int j = 0; j < 8; j++) {
            int col = warp_n * 64 + j * 8 + 2 * (lane & 3);
            float b0 = bias[col], b1 = bias[col + 1];
            float u0 = u[col],    u1 = u[col + 1];
            r0acc += tanh_fast(acc[mt][j][0] + b0) * u0
                   + tanh_fast(acc[mt][j][1] + b1) * u1;
            r1acc += tanh_fast(acc[mt][j][2] + b0) * u0
                   + tanh_fast(acc[mt][j][3] + b1) * u1;
        }
        r0acc += __shfl_xor_sync(0xffffffffu, r0acc, 1);
        r0acc += __shfl_xor_sync(0xffffffffu, r0acc, 2);
        r1acc += __shfl_xor_sync(0xffffffffu, r1acc, 1);
        r1acc += __shfl_xor_sync(0xffffffffu, r1acc, 2);
        if ((lane & 3) == 0) {
            int lrow = warp_m * 32 + mt * 16 + (lane >> 2);
            atomicAdd(&sm_red[lrow],     r0acc);
            atomicAdd(&sm_red[lrow + 8], r1acc);
        }
    }
    __syncthreads();
    if (tid < 128) g_logits[row0 + tid] = sm_red[tid];
}

// ---------------------------------------------------------------------------
// Kernel B: per-batch masked softmax over S (mask int32). Zeroes out[b].
// ---------------------------------------------------------------------------
__global__ __launch_bounds__(256) void softmax_kernel(
    const int* __restrict__ mask, float* __restrict__ out)
{
    const int b = blockIdx.x;
    const int tid = threadIdx.x;
    __shared__ float red[256];

    out[b * 512 + tid] = 0.f;
    out[b * 512 + 256 + tid] = 0.f;

    float local = 0.f;
    for (int s = tid; s < S_; s += 256) {
        float e = expf(g_logits[b * S_ + s]);
        e = (mask[b * S_ + s] != 0) ? e : 0.f;
        g_wts[b * S_ + s] = e;
        local += e;
    }
    red[tid] = local;
    __syncthreads();
#pragma unroll
    for (int off = 128; off > 0; off >>= 1) {
        if (tid < off) red[tid] += red[tid + off];
        __syncthreads();
    }
    const float inv = 1.f / (red[0] + 1e-7f);
    for (int s = tid; s < S_; s += 256)
        g_wts[b * S_ + s] *= inv;
}

// ---------------------------------------------------------------------------
// Kernel C: out[b,d] += sum_{s chunk} x[b,s,d] * w[b,s]
// float4 per thread: 4 independent FMA chains, 4x MLP, fully coalesced.
// Thread t: group g = t>>7 handles s = s0+g, s0+g+4, ...; cols 4*(t&127).
// ---------------------------------------------------------------------------
#define SCHUNK 256
__global__ __launch_bounds__(512) void wsum_kernel(
    const float* __restrict__ x, float* __restrict__ out)
{
    const int b = blockIdx.x;
    const int s0 = blockIdx.y * SCHUNK;
    const int g = threadIdx.x >> 7;          // 0..3
    const int d4 = (threadIdx.x & 127) * 4;  // column group

    __shared__ float wsh[SCHUNK];
    for (int i = threadIdx.x; i < SCHUNK; i += 512)
        wsh[i] = g_wts[b * S_ + s0 + i];
    __syncthreads();

    float4 acc = make_float4(0.f, 0.f, 0.f, 0.f);
    const float* xp = x + ((long)b * S_ + s0) * D_ + d4;
#pragma unroll 8
    for (int s = g; s < SCHUNK; s += 4) {
        float4 v = *(const float4*)(xp + (long)s * D_);
        float w = wsh[s];
        acc.x = fmaf(v.x, w, acc.x);
        acc.y = fmaf(v.y, w, acc.y);
        acc.z = fmaf(v.z, w, acc.z);
        acc.w = fmaf(v.w, w, acc.w);
    }

    atomicAdd(&out[b * D_ + d4 + 0], acc.x);
    atomicAdd(&out[b * D_ + d4 + 1], acc.y);
    atomicAdd(&out[b * D_ + d4 + 2], acc.z);
    atomicAdd(&out[b * D_ + d4 + 3], acc.w);
}

// ---------------------------------------------------------------------------
extern "C" void kernel_launch(void* const* d_in, const int* in_sizes, int n_in,
                              void* d_out, int out_size)
{
    const float* x    = (const float*)d_in[0];
    const int*   mask = (const int*)d_in[1];
    const float* W    = (const float*)d_in[2];
    const float* bias = (const float*)d_in[3];
    const float* u    = (const float*)d_in[4];
    float*       out  = (float*)d_out;

    cudaFuncSetAttribute(logits_mma_kernel,
                         cudaFuncAttributeMaxDynamicSharedMemorySize, SMEM_BYTES);

    wprep_kernel<<<512, 256>>>(W);
    logits_mma_kernel<<<BS_ / 128, 512, SMEM_BYTES>>>(x, bias, u);
    softmax_kernel<<<B_, 256>>>(mask, out);
    wsum_kernel<<<dim3(B_, S_ / SCHUNK), 512>>>(x, out);
}

// round 7
// speedup vs baseline: 4.5314x; 1.4913x over previous
#include <cuda_runtime.h>
#include <cuda_fp16.h>
#include <math.h>
#include <stdint.h>

#define B_ 64
#define S_ 2048
#define D_ 512
#define A_ 256
#define BS_ (B_ * S_)

// Scratch (allocation-free rule: __device__ globals)
__device__ float g_logits[BS_];
__device__ float g_wts[BS_];
// W transposed fp16: WT[a][d] (== col-major B for mma .row.col)
__device__ __half g_WT[A_ * D_];

// ---------------------------------------------------------------------------
// helpers
// ---------------------------------------------------------------------------
__device__ __forceinline__ uint32_t smem_u32(const void* p) {
    uint32_t a;
    asm("{ .reg .u64 t; cvta.to.shared.u64 t, %1; cvt.u32.u64 %0, t; }"
        : "=r"(a) : "l"(p));
    return a;
}

__device__ __forceinline__ void ldsm_x4(uint32_t addr, uint32_t& r0, uint32_t& r1,
                                        uint32_t& r2, uint32_t& r3) {
    asm volatile("ldmatrix.sync.aligned.m8n8.x4.shared.b16 {%0,%1,%2,%3}, [%4];"
                 : "=r"(r0), "=r"(r1), "=r"(r2), "=r"(r3) : "r"(addr));
}

__device__ __forceinline__ void mma_f16(float* d, const uint32_t* a,
                                        uint32_t b0, uint32_t b1) {
    asm volatile(
        "mma.sync.aligned.m16n8k16.row.col.f32.f16.f16.f32 "
        "{%0,%1,%2,%3}, {%4,%5,%6,%7}, {%8,%9}, {%0,%1,%2,%3};"
        : "+f"(d[0]), "+f"(d[1]), "+f"(d[2]), "+f"(d[3])
        : "r"(a[0]), "r"(a[1]), "r"(a[2]), "r"(a[3]), "r"(b0), "r"(b1));
}

__device__ __forceinline__ void cp16(uint32_t saddr, const void* gptr) {
    asm volatile("cp.async.cg.shared.global [%0], [%1], 16;"
                 :: "r"(saddr), "l"(gptr));
}
__device__ __forceinline__ void cp_commit() {
    asm volatile("cp.async.commit_group;" ::: "memory");
}
__device__ __forceinline__ void cp_wait0() {
    asm volatile("cp.async.wait_group 0;" ::: "memory");
}

__device__ __forceinline__ uint32_t pack_h2(float a, float b) {
    __half2 h = __floats2half2_rn(a, b);
    return *(uint32_t*)&h;
}

// tanh via ex2/rcp MUFU path: err ~1e-6
__device__ __forceinline__ float tanh_fast(float x) {
    float e = __expf(2.f * x);
    return 1.f - __fdividef(2.f, e + 1.f);
}

// ---------------------------------------------------------------------------
// Kernel W-prep: WT[a][d] = fp16(W[d][a])
// ---------------------------------------------------------------------------
__global__ void wprep_kernel(const float* __restrict__ W) {
    int idx = blockIdx.x * 256 + threadIdx.x;   // 0..131071
    int d = idx >> 8, a = idx & 255;
    g_WT[a * D_ + d] = __float2half_rn(W[d * A_ + a]);
}

// ---------------------------------------------------------------------------
// Kernel A: mma.sync fp16 single-term GEMM, 128 rows x 256 cols per CTA, K=512.
// D = fp16(x) * fp16(W): both quantization errors ~2^-12, independent.
// 512 threads = 16 warps in 4(m) x 4(n); warp tile 32x64.
// SMEM rows padded to 80B -> conflict-free ldmatrix.
// x + W double-buffered; one barrier + one cp wait per chunk.
// Fused tanh+u epilogue -> g_logits.
// ---------------------------------------------------------------------------
#define TKC 32
#define NCHUNK (D_ / TKC)           // 16
#define XROW 80                     // 32 fp16 = 64B, padded to 80
#define XBUF (128 * XROW)                   // 10240 per stage
#define OFF_XH 0                            // [2 stages]
#define OFF_W  (2 * XBUF)                   // 20480, [2 stages]
#define WSTAGE (256 * XROW)                 // 20480 per stage
#define OFF_RED (OFF_W + 2 * WSTAGE)        // 61440
#define SMEM_BYTES (OFF_RED + 512)          // 61952

__global__ __launch_bounds__(512, 1) void logits_mma_kernel(
    const float* __restrict__ x, const float* __restrict__ bias,
    const float* __restrict__ u)
{
    extern __shared__ char smem[];
    const uint32_t sb = smem_u32(smem);
    float* sm_red = (float*)(smem + OFF_RED);

    const int tid  = threadIdx.x;
    const int wid  = tid >> 5;
    const int lane = tid & 31;
    const int warp_m = wid & 3;          // row group (32 rows)
    const int warp_n = wid >> 2;         // col group (64 cols)
    const long row0 = (long)blockIdx.x * 128;

    if (tid < 128) sm_red[tid] = 0.f;

    // x staging mapping: 4 threads per row, 8 floats each
    const int row_x = tid >> 2;
    const int kq_x  = (tid & 3) * 8;
    const float* gx = x + (row0 + row_x) * D_ + kq_x;
    const uint32_t xoff = (uint32_t)(row_x * XROW + kq_x * 2);

    // W cp.async mapping: 2 threads per row (n), 2x16B each
    const int n_w  = tid >> 1;
    const int half = tid & 1;
    const __half* gw = g_WT + n_w * D_ + half * 16;
    const uint32_t wdst_row = n_w * XROW + half * 32;

    float acc[2][8][4];
#pragma unroll
    for (int i = 0; i < 2; i++)
#pragma unroll
        for (int j = 0; j < 8; j++)
#pragma unroll
            for (int k = 0; k < 4; k++) acc[i][j][k] = 0.f;

    // ---- preload chunk 0 ----
    {
        float4 v0 = *(const float4*)(gx);
        float4 v1 = *(const float4*)(gx + 4);
        uint4 hi;
        hi.x = pack_h2(v0.x, v0.y); hi.y = pack_h2(v0.z, v0.w);
        hi.z = pack_h2(v1.x, v1.y); hi.w = pack_h2(v1.z, v1.w);
        *(uint4*)(smem + OFF_XH + xoff) = hi;

        uint32_t wb = sb + OFF_W;
        cp16(wb + wdst_row,      gw);
        cp16(wb + wdst_row + 16, gw + 8);
        cp_commit();
    }

    // ldmatrix lane addressing (constant across chunks)
    const int a_row  = (lane & 15);
    const int a_kb   = (lane >> 4) * 16;
    const int t      = lane >> 3;
    const int b_noff = (lane & 7) + 8 * (t >> 1);
    const int b_kb   = 16 * (t & 1);

    for (int c = 0; c < NCHUNK; c++) {
        const int st  = c & 1;
        const int stn = (c + 1) & 1;

        cp_wait0();          // W chunk c resident
        __syncthreads();     // x chunk c stores visible; stage stn free

        // kick off W chunk c+1 (async, overlaps mma)
        if (c + 1 < NCHUNK) {
            uint32_t wb = sb + OFF_W + stn * WSTAGE;
            const __half* sh = gw + (c + 1) * TKC;
            cp16(wb + wdst_row,      sh);
            cp16(wb + wdst_row + 16, sh + 8);
            cp_commit();
        }
        // x chunk c+1 global loads (in flight during mma)
        float4 xv0, xv1;
        if (c + 1 < NCHUNK) {
            xv0 = *(const float4*)(gx + (c + 1) * TKC);
            xv1 = *(const float4*)(gx + (c + 1) * TKC + 4);
        }

        const uint32_t xh = sb + OFF_XH + st * XBUF;
        const uint32_t wh = sb + OFF_W + st * WSTAGE;

#pragma unroll
        for (int ks = 0; ks < 2; ks++) {
            uint32_t ah[2][4];
#pragma unroll
            for (int mt = 0; mt < 2; mt++) {
                uint32_t ra = (warp_m * 32 + mt * 16 + a_row) * XROW + ks * 32 + a_kb;
                ldsm_x4(xh + ra, ah[mt][0], ah[mt][1], ah[mt][2], ah[mt][3]);
            }
#pragma unroll
            for (int pair = 0; pair < 4; pair++) {
                uint32_t rb = (warp_n * 64 + pair * 16 + b_noff) * XROW + ks * 32 + b_kb;
                uint32_t bh0, bh1, bh2, bh3;
                ldsm_x4(wh + rb, bh0, bh1, bh2, bh3);
#pragma unroll
                for (int mt = 0; mt < 2; mt++) {
                    mma_f16(acc[mt][pair * 2 + 0], ah[mt], bh0, bh1);
                    mma_f16(acc[mt][pair * 2 + 1], ah[mt], bh2, bh3);
                }
            }
        }

        // store x chunk c+1 into stage stn (readers finished chunk c-1)
        if (c + 1 < NCHUNK) {
            uint4 hi;
            hi.x = pack_h2(xv0.x, xv0.y); hi.y = pack_h2(xv0.z, xv0.w);
            hi.z = pack_h2(xv1.x, xv1.y); hi.w = pack_h2(xv1.z, xv1.w);
            *(uint4*)(smem + OFF_XH + stn * XBUF + xoff) = hi;
        }
    }

    // ---- epilogue: tanh(acc + bias) * u, reduce over 256 cols per row ----
#pragma unroll
    for (int mt = 0; mt < 2; mt++) {
        float r0acc = 0.f, r1acc = 0.f;
#pragma unroll
        for (int j = 0; j < 8; j++) {
            int col = warp_n * 64 + j * 8 + 2 * (lane & 3);
            float b0 = bias[col], b1 = bias[col + 1];
            float u0 = u[col],    u1 = u[col + 1];
            r0acc += tanh_fast(acc[mt][j][0] + b0) * u0
                   + tanh_fast(acc[mt][j][1] + b1) * u1;
            r1acc += tanh_fast(acc[mt][j][2] + b0) * u0
                   + tanh_fast(acc[mt][j][3] + b1) * u1;
        }
        r0acc += __shfl_xor_sync(0xffffffffu, r0acc, 1);
        r0acc += __shfl_xor_sync(0xffffffffu, r0acc, 2);
        r1acc += __shfl_xor_sync(0xffffffffu, r1acc, 1);
        r1acc += __shfl_xor_sync(0xffffffffu, r1acc, 2);
        if ((lane & 3) == 0) {
            int lrow = warp_m * 32 + mt * 16 + (lane >> 2);
            atomicAdd(&sm_red[lrow],     r0acc);
            atomicAdd(&sm_red[lrow + 8], r1acc);
        }
    }
    __syncthreads();
    if (tid < 128) g_logits[row0 + tid] = sm_red[tid];
}

// ---------------------------------------------------------------------------
// Kernel B: per-batch masked softmax over S (mask int32). Zeroes out[b].
// ---------------------------------------------------------------------------
__global__ __launch_bounds__(256) void softmax_kernel(
    const int* __restrict__ mask, float* __restrict__ out)
{
    const int b = blockIdx.x;
    const int tid = threadIdx.x;
    __shared__ float red[256];

    out[b * 512 + tid] = 0.f;
    out[b * 512 + 256 + tid] = 0.f;

    float local = 0.f;
    for (int s = tid; s < S_; s += 256) {
        float e = expf(g_logits[b * S_ + s]);
        e = (mask[b * S_ + s] != 0) ? e : 0.f;
        g_wts[b * S_ + s] = e;
        local += e;
    }
    red[tid] = local;
    __syncthreads();
#pragma unroll
    for (int off = 128; off > 0; off >>= 1) {
        if (tid < off) red[tid] += red[tid + off];
        __syncthreads();
    }
    const float inv = 1.f / (red[0] + 1e-7f);
    for (int s = tid; s < S_; s += 256)
        g_wts[b * S_ + s] *= inv;
}

// ---------------------------------------------------------------------------
// Kernel C: out[b,d] += sum_{s chunk} x[b,s,d] * w[b,s]
// float4 per thread: 4 independent FMA chains, fully coalesced.
// ---------------------------------------------------------------------------
#define SCHUNK 256
__global__ __launch_bounds__(512) void wsum_kernel(
    const float* __restrict__ x, float* __restrict__ out)
{
    const int b = blockIdx.x;
    const int s0 = blockIdx.y * SCHUNK;
    const int g = threadIdx.x >> 7;          // 0..3
    const int d4 = (threadIdx.x & 127) * 4;  // column group

    __shared__ float wsh[SCHUNK];
    for (int i = threadIdx.x; i < SCHUNK; i += 512)
        wsh[i] = g_wts[b * S_ + s0 + i];
    __syncthreads();

    float4 acc = make_float4(0.f, 0.f, 0.f, 0.f);
    const float* xp = x + ((long)b * S_ + s0) * D_ + d4;
#pragma unroll 16
    for (int s = g; s < SCHUNK; s += 4) {
        float4 v = *(const float4*)(xp + (long)s * D_);
        float w = wsh[s];
        acc.x = fmaf(v.x, w, acc.x);
        acc.y = fmaf(v.y, w, acc.y);
        acc.z = fmaf(v.z, w, acc.z);
        acc.w = fmaf(v.w, w, acc.w);
    }

    atomicAdd(&out[b * D_ + d4 + 0], acc.x);
    atomicAdd(&out[b * D_ + d4 + 1], acc.y);
    atomicAdd(&out[b * D_ + d4 + 2], acc.z);
    atomicAdd(&out[b * D_ + d4 + 3], acc.w);
}

// ---------------------------------------------------------------------------
extern "C" void kernel_launch(void* const* d_in, const int* in_sizes, int n_in,
                              void* d_out, int out_size)
{
    const float* x    = (const float*)d_in[0];
    const int*   mask = (const int*)d_in[1];
    const float* W    = (const float*)d_in[2];
    const float* bias = (const float*)d_in[3];
    const float* u    = (const float*)d_in[4];
    float*       out  = (float*)d_out;

    cudaFuncSetAttribute(logits_mma_kernel,
                         cudaFuncAttributeMaxDynamicSharedMemorySize, SMEM_BYTES);

    wprep_kernel<<<512, 256>>>(W);
    logits_mma_kernel<<<BS_ / 128, 512, SMEM_BYTES>>>(x, bias, u);
    softmax_kernel<<<B_, 256>>>(mask, out);
    wsum_kernel<<<dim3(B_, S_ / SCHUNK), 512>>>(x, out);
}

// round 8
// speedup vs baseline: 4.6726x; 1.0312x over previous
#include <cuda_runtime.h>
#include <cuda_fp16.h>
#include <math.h>
#include <stdint.h>

#define B_ 64
#define S_ 2048
#define D_ 512
#define A_ 256
#define BS_ (B_ * S_)

// Scratch (allocation-free rule: __device__ globals)
__device__ float g_logits[BS_];
__device__ float g_wts[BS_];
__device__ __half g_WT[A_ * D_];        // W^T fp16 (col-major B for mma)
__device__ __half g_xh[(size_t)BS_ * D_];  // fp16 copy of x (written by kernel A)

// ---------------------------------------------------------------------------
// helpers
// ---------------------------------------------------------------------------
__device__ __forceinline__ uint32_t smem_u32(const void* p) {
    uint32_t a;
    asm("{ .reg .u64 t; cvta.to.shared.u64 t, %1; cvt.u32.u64 %0, t; }"
        : "=r"(a) : "l"(p));
    return a;
}

__device__ __forceinline__ void ldsm_x4(uint32_t addr, uint32_t& r0, uint32_t& r1,
                                        uint32_t& r2, uint32_t& r3) {
    asm volatile("ldmatrix.sync.aligned.m8n8.x4.shared.b16 {%0,%1,%2,%3}, [%4];"
                 : "=r"(r0), "=r"(r1), "=r"(r2), "=r"(r3) : "r"(addr));
}

__device__ __forceinline__ void mma_f16(float* d, const uint32_t* a,
                                        uint32_t b0, uint32_t b1) {
    asm volatile(
        "mma.sync.aligned.m16n8k16.row.col.f32.f16.f16.f32 "
        "{%0,%1,%2,%3}, {%4,%5,%6,%7}, {%8,%9}, {%0,%1,%2,%3};"
        : "+f"(d[0]), "+f"(d[1]), "+f"(d[2]), "+f"(d[3])
        : "r"(a[0]), "r"(a[1]), "r"(a[2]), "r"(a[3]), "r"(b0), "r"(b1));
}

__device__ __forceinline__ void cp16(uint32_t saddr, const void* gptr) {
    asm volatile("cp.async.cg.shared.global [%0], [%1], 16;"
                 :: "r"(saddr), "l"(gptr));
}
__device__ __forceinline__ void cp_commit() {
    asm volatile("cp.async.commit_group;" ::: "memory");
}
__device__ __forceinline__ void cp_wait0() {
    asm volatile("cp.async.wait_group 0;" ::: "memory");
}

__device__ __forceinline__ uint32_t pack_h2(float a, float b) {
    __half2 h = __floats2half2_rn(a, b);
    return *(uint32_t*)&h;
}

// tanh via ex2/rcp MUFU path: err ~1e-6
__device__ __forceinline__ float tanh_fast(float x) {
    float e = __expf(2.f * x);
    return 1.f - __fdividef(2.f, e + 1.f);
}

// ---------------------------------------------------------------------------
// Kernel W-prep: WT[a][d] = fp16(W[d][a])
// ---------------------------------------------------------------------------
__global__ void wprep_kernel(const float* __restrict__ W) {
    int idx = blockIdx.x * 256 + threadIdx.x;   // 0..131071
    int d = idx >> 8, a = idx & 255;
    g_WT[a * D_ + d] = __float2half_rn(W[d * A_ + a]);
}

// ---------------------------------------------------------------------------
// Kernel A: mma.sync fp16 GEMM, 128 rows x 256 cols per CTA, K=512.
// Also streams the fp16(x) conversion out to g_xh for the wsum kernel.
// 512 threads = 16 warps in 4(m) x 4(n); warp tile 32x64.
// SMEM rows padded to 80B -> conflict-free ldmatrix.
// x + W double-buffered; one barrier + one cp wait per chunk.
// Fused tanh+u epilogue -> g_logits.
// ---------------------------------------------------------------------------
#define TKC 32
#define NCHUNK (D_ / TKC)           // 16
#define XROW 80                     // 32 fp16 = 64B, padded to 80
#define XBUF (128 * XROW)                   // 10240 per stage
#define OFF_XH 0                            // [2 stages]
#define OFF_W  (2 * XBUF)                   // 20480, [2 stages]
#define WSTAGE (256 * XROW)                 // 20480 per stage
#define OFF_RED (OFF_W + 2 * WSTAGE)        // 61440
#define SMEM_BYTES (OFF_RED + 512)          // 61952

__global__ __launch_bounds__(512, 1) void logits_mma_kernel(
    const float* __restrict__ x, const float* __restrict__ bias,
    const float* __restrict__ u)
{
    extern __shared__ char smem[];
    const uint32_t sb = smem_u32(smem);
    float* sm_red = (float*)(smem + OFF_RED);

    const int tid  = threadIdx.x;
    const int wid  = tid >> 5;
    const int lane = tid & 31;
    const int warp_m = wid & 3;          // row group (32 rows)
    const int warp_n = wid >> 2;         // col group (64 cols)
    const long row0 = (long)blockIdx.x * 128;

    if (tid < 128) sm_red[tid] = 0.f;

    // x staging mapping: 4 threads per row, 8 floats each
    const int row_x = tid >> 2;
    const int kq_x  = (tid & 3) * 8;
    const float* gx = x + (row0 + row_x) * D_ + kq_x;
    __half* gxh_out = g_xh + (size_t)(row0 + row_x) * D_ + kq_x;
    const uint32_t xoff = (uint32_t)(row_x * XROW + kq_x * 2);

    // W cp.async mapping: 2 threads per row (n), 2x16B each
    const int n_w  = tid >> 1;
    const int half = tid & 1;
    const __half* gw = g_WT + n_w * D_ + half * 16;
    const uint32_t wdst_row = n_w * XROW + half * 32;

    float acc[2][8][4];
#pragma unroll
    for (int i = 0; i < 2; i++)
#pragma unroll
        for (int j = 0; j < 8; j++)
#pragma unroll
            for (int k = 0; k < 4; k++) acc[i][j][k] = 0.f;

    // ---- preload chunk 0 ----
    {
        float4 v0 = *(const float4*)(gx);
        float4 v1 = *(const float4*)(gx + 4);
        uint4 hi;
        hi.x = pack_h2(v0.x, v0.y); hi.y = pack_h2(v0.z, v0.w);
        hi.z = pack_h2(v1.x, v1.y); hi.w = pack_h2(v1.z, v1.w);
        *(uint4*)(smem + OFF_XH + xoff) = hi;
        *(uint4*)(gxh_out) = hi;           // stream fp16 x copy

        uint32_t wb = sb + OFF_W;
        cp16(wb + wdst_row,      gw);
        cp16(wb + wdst_row + 16, gw + 8);
        cp_commit();
    }

    // ldmatrix lane addressing (constant across chunks)
    const int a_row  = (lane & 15);
    const int a_kb   = (lane >> 4) * 16;
    const int t      = lane >> 3;
    const int b_noff = (lane & 7) + 8 * (t >> 1);
    const int b_kb   = 16 * (t & 1);

    for (int c = 0; c < NCHUNK; c++) {
        const int st  = c & 1;
        const int stn = (c + 1) & 1;

        cp_wait0();          // W chunk c resident
        __syncthreads();     // x chunk c stores visible; stage stn free

        // kick off W chunk c+1 (async, overlaps mma)
        if (c + 1 < NCHUNK) {
            uint32_t wb = sb + OFF_W + stn * WSTAGE;
            const __half* sh = gw + (c + 1) * TKC;
            cp16(wb + wdst_row,      sh);
            cp16(wb + wdst_row + 16, sh + 8);
            cp_commit();
        }
        // x chunk c+1 global loads (in flight during mma)
        float4 xv0, xv1;
        if (c + 1 < NCHUNK) {
            xv0 = *(const float4*)(gx + (c + 1) * TKC);
            xv1 = *(const float4*)(gx + (c + 1) * TKC + 4);
        }

        const uint32_t xh = sb + OFF_XH + st * XBUF;
        const uint32_t wh = sb + OFF_W + st * WSTAGE;

#pragma unroll
        for (int ks = 0; ks < 2; ks++) {
            uint32_t ah[2][4];
#pragma unroll
            for (int mt = 0; mt < 2; mt++) {
                uint32_t ra = (warp_m * 32 + mt * 16 + a_row) * XROW + ks * 32 + a_kb;
                ldsm_x4(xh + ra, ah[mt][0], ah[mt][1], ah[mt][2], ah[mt][3]);
            }
#pragma unroll
            for (int pair = 0; pair < 4; pair++) {
                uint32_t rb = (warp_n * 64 + pair * 16 + b_noff) * XROW + ks * 32 + b_kb;
                uint32_t bh0, bh1, bh2, bh3;
                ldsm_x4(wh + rb, bh0, bh1, bh2, bh3);
#pragma unroll
                for (int mt = 0; mt < 2; mt++) {
                    mma_f16(acc[mt][pair * 2 + 0], ah[mt], bh0, bh1);
                    mma_f16(acc[mt][pair * 2 + 1], ah[mt], bh2, bh3);
                }
            }
        }

        // store x chunk c+1 into stage stn + stream fp16 copy to global
        if (c + 1 < NCHUNK) {
            uint4 hi;
            hi.x = pack_h2(xv0.x, xv0.y); hi.y = pack_h2(xv0.z, xv0.w);
            hi.z = pack_h2(xv1.x, xv1.y); hi.w = pack_h2(xv1.z, xv1.w);
            *(uint4*)(smem + OFF_XH + stn * XBUF + xoff) = hi;
            *(uint4*)(gxh_out + (c + 1) * TKC) = hi;
        }
    }

    // ---- epilogue: tanh(acc + bias) * u, reduce over 256 cols per row ----
#pragma unroll
    for (int mt = 0; mt < 2; mt++) {
        float r0acc = 0.f, r1acc = 0.f;
#pragma unroll
        for (int j = 0; j < 8; j++) {
            int col = warp_n * 64 + j * 8 + 2 * (lane & 3);
            float b0 = bias[col], b1 = bias[col + 1];
            float u0 = u[col],    u1 = u[col + 1];
            r0acc += tanh_fast(acc[mt][j][0] + b0) * u0
                   + tanh_fast(acc[mt][j][1] + b1) * u1;
            r1acc += tanh_fast(acc[mt][j][2] + b0) * u0
                   + tanh_fast(acc[mt][j][3] + b1) * u1;
        }
        r0acc += __shfl_xor_sync(0xffffffffu, r0acc, 1);
        r0acc += __shfl_xor_sync(0xffffffffu, r0acc, 2);
        r1acc += __shfl_xor_sync(0xffffffffu, r1acc, 1);
        r1acc += __shfl_xor_sync(0xffffffffu, r1acc, 2);
        if ((lane & 3) == 0) {
            int lrow = warp_m * 32 + mt * 16 + (lane >> 2);
            atomicAdd(&sm_red[lrow],     r0acc);
            atomicAdd(&sm_red[lrow + 8], r1acc);
        }
    }
    __syncthreads();
    if (tid < 128) g_logits[row0 + tid] = sm_red[tid];
}

// ---------------------------------------------------------------------------
// Kernel B: per-batch masked softmax over S (mask int32). Zeroes out[b].
// 1024 threads: 2 elements per thread, shuffle+smem reduce.
// ---------------------------------------------------------------------------
__global__ __launch_bounds__(1024) void softmax_kernel(
    const int* __restrict__ mask, float* __restrict__ out)
{
    const int b = blockIdx.x;
    const int tid = threadIdx.x;
    __shared__ float red[32];

    if (tid < 512) out[b * 512 + tid] = 0.f;

    float e0 = expf(g_logits[b * S_ + tid]);
    float e1 = expf(g_logits[b * S_ + 1024 + tid]);
    e0 = (mask[b * S_ + tid] != 0) ? e0 : 0.f;
    e1 = (mask[b * S_ + 1024 + tid] != 0) ? e1 : 0.f;

    float local = e0 + e1;
#pragma unroll
    for (int off = 16; off > 0; off >>= 1)
        local += __shfl_xor_sync(0xffffffffu, local, off);
    if ((tid & 31) == 0) red[tid >> 5] = local;
    __syncthreads();
    if (tid < 32) {
        float v = red[tid];
#pragma unroll
        for (int off = 16; off > 0; off >>= 1)
            v += __shfl_xor_sync(0xffffffffu, v, off);
        if (tid == 0) red[0] = 1.f / (v + 1e-7f);
    }
    __syncthreads();
    const float inv = red[0];
    g_wts[b * S_ + tid]        = e0 * inv;
    g_wts[b * S_ + 1024 + tid] = e1 * inv;
}

// ---------------------------------------------------------------------------
// Kernel C: out[b,d] += sum_{s chunk} xh[b,s,d] * w[b,s]   (fp16 x, half bytes)
// 64 threads cover one row (8 cols each, uint4=8 halves); 8 rows in flight.
// ---------------------------------------------------------------------------
#define SCHUNK 256
__global__ __launch_bounds__(512) void wsum_kernel(float* __restrict__ out)
{
    const int b = blockIdx.x;
    const int s0 = blockIdx.y * SCHUNK;
    const int g = threadIdx.x >> 6;          // 0..7
    const int d8 = (threadIdx.x & 63) * 8;   // column group

    __shared__ float wsh[SCHUNK];
    for (int i = threadIdx.x; i < SCHUNK; i += 512)
        wsh[i] = g_wts[b * S_ + s0 + i];
    __syncthreads();

    float acc[8];
#pragma unroll
    for (int i = 0; i < 8; i++) acc[i] = 0.f;

    const __half* xp = g_xh + ((size_t)b * S_ + s0) * D_ + d8;
#pragma unroll 8
    for (int s = g; s < SCHUNK; s += 8) {
        uint4 v = *(const uint4*)(xp + (size_t)s * D_);
        float w = wsh[s];
        float2 f0 = __half22float2(*(__half2*)&v.x);
        float2 f1 = __half22float2(*(__half2*)&v.y);
        float2 f2 = __half22float2(*(__half2*)&v.z);
        float2 f3 = __half22float2(*(__half2*)&v.w);
        acc[0] = fmaf(f0.x, w, acc[0]); acc[1] = fmaf(f0.y, w, acc[1]);
        acc[2] = fmaf(f1.x, w, acc[2]); acc[3] = fmaf(f1.y, w, acc[3]);
        acc[4] = fmaf(f2.x, w, acc[4]); acc[5] = fmaf(f2.y, w, acc[5]);
        acc[6] = fmaf(f3.x, w, acc[6]); acc[7] = fmaf(f3.y, w, acc[7]);
    }

#pragma unroll
    for (int i = 0; i < 8; i++)
        atomicAdd(&out[b * D_ + d8 + i], acc[i]);
}

// ---------------------------------------------------------------------------
extern "C" void kernel_launch(void* const* d_in, const int* in_sizes, int n_in,
                              void* d_out, int out_size)
{
    const float* x    = (const float*)d_in[0];
    const int*   mask = (const int*)d_in[1];
    const float* W    = (const float*)d_in[2];
    const float* bias = (const float*)d_in[3];
    const float* u    = (const float*)d_in[4];
    float*       out  = (float*)d_out;

    cudaFuncSetAttribute(logits_mma_kernel,
                         cudaFuncAttributeMaxDynamicSharedMemorySize, SMEM_BYTES);

    wprep_kernel<<<512, 256>>>(W);
    logits_mma_kernel<<<BS_ / 128, 512, SMEM_BYTES>>>(x, bias, u);
    softmax_kernel<<<B_, 1024>>>(mask, out);
    wsum_kernel<<<dim3(B_, S_ / SCHUNK), 512>>>(out);
}

// round 9
// speedup vs baseline: 7.6695x; 1.6414x over previous
#include <cuda_runtime.h>
#include <cuda_fp16.h>
#include <math.h>
#include <stdint.h>

#define B_ 64
#define S_ 2048
#define D_ 512
#define A_ 256
#define BS_ (B_ * S_)

// Scratch (allocation-free rule: __device__ globals)
__device__ int    g_idx[BS_];           // per-batch compacted active s indices
__device__ int    g_cnt[B_];            // active count per batch
__device__ float  g_esum[B_];           // per-batch sum of exp(logit) over active
__device__ float  g_ewts[BS_];          // compacted exp(logit)
__device__ __half g_WT[A_ * D_];        // W^T fp16 (col-major B for mma)
__device__ __half g_xh[(size_t)BS_ * D_]; // compacted fp16 x rows
// ---------------------------------------------------------------------------
// helpers
// ---------------------------------------------------------------------------
__device__ __forceinline__ uint32_t smem_u32(const void* p) {
    uint32_t a;
    asm("{ .reg .u64 t; cvta.to.shared.u64 t, %1; cvt.u32.u64 %0, t; }"
        : "=r"(a) : "l"(p));
    return a;
}

__device__ __forceinline__ void ldsm_x4(uint32_t addr, uint32_t& r0, uint32_t& r1,
                                        uint32_t& r2, uint32_t& r3) {
    asm volatile("ldmatrix.sync.aligned.m8n8.x4.shared.b16 {%0,%1,%2,%3}, [%4];"
                 : "=r"(r0), "=r"(r1), "=r"(r2), "=r"(r3) : "r"(addr));
}

__device__ __forceinline__ void mma_f16(float* d, const uint32_t* a,
                                        uint32_t b0, uint32_t b1) {
    asm volatile(
        "mma.sync.aligned.m16n8k16.row.col.f32.f16.f16.f32 "
        "{%0,%1,%2,%3}, {%4,%5,%6,%7}, {%8,%9}, {%0,%1,%2,%3};"
        : "+f"(d[0]), "+f"(d[1]), "+f"(d[2]), "+f"(d[3])
        : "r"(a[0]), "r"(a[1]), "r"(a[2]), "r"(a[3]), "r"(b0), "r"(b1));
}

__device__ __forceinline__ void cp16(uint32_t saddr, const void* gptr) {
    asm volatile("cp.async.cg.shared.global [%0], [%1], 16;"
                 :: "r"(saddr), "l"(gptr));
}
__device__ __forceinline__ void cp_commit() {
    asm volatile("cp.async.commit_group;" ::: "memory");
}
__device__ __forceinline__ void cp_wait0() {
    asm volatile("cp.async.wait_group 0;" ::: "memory");
}

__device__ __forceinline__ uint32_t pack_h2(float a, float b) {
    __half2 h = __floats2half2_rn(a, b);
    return *(uint32_t*)&h;
}

// tanh via ex2/rcp MUFU path: err ~1e-6
__device__ __forceinline__ float tanh_fast(float x) {
    float e = __expf(2.f * x);
    return 1.f - __fdividef(2.f, e + 1.f);
}

// ---------------------------------------------------------------------------
// Kernel 0: per-batch mask compaction (+ zero out[b], g_esum[b])
// 256 threads, 8 s-values each; warp shuffle scan + cross-warp scan.
// ---------------------------------------------------------------------------
__global__ __launch_bounds__(256) void compact_kernel(
    const int* __restrict__ mask, float* __restrict__ out)
{
    const int b = blockIdx.x;
    const int tid = threadIdx.x;
    const int lane = tid & 31, w = tid >> 5;
    __shared__ int wbase[8];

    out[b * 512 + tid] = 0.f;
    out[b * 512 + 256 + tid] = 0.f;
    if (tid == 0) g_esum[b] = 0.f;

    int loc[8];
    int c = 0;
    const int* mp = mask + b * S_ + tid * 8;
#pragma unroll
    for (int i = 0; i < 8; i++)
        if (mp[i] != 0) loc[c++] = tid * 8 + i;

    int inc = c;
#pragma unroll
    for (int off = 1; off < 32; off <<= 1) {
        int n = __shfl_up_sync(0xffffffffu, inc, off);
        if (lane >= off) inc += n;
    }
    if (lane == 31) wbase[w] = inc;
    __syncthreads();
    if (tid == 0) {
        int r = 0;
#pragma unroll
        for (int i = 0; i < 8; i++) { int t = wbase[i]; wbase[i] = r; r += t; }
        g_cnt[b] = r;
    }
    __syncthreads();
    int base = wbase[w] + inc - c;
    for (int i = 0; i < c; i++)
        g_idx[b * S_ + base + i] = loc[i];
}

// ---------------------------------------------------------------------------
// Kernel W-prep: WT[a][d] = fp16(W[d][a])
// ---------------------------------------------------------------------------
__global__ void wprep_kernel(const float* __restrict__ W) {
    int idx = blockIdx.x * 256 + threadIdx.x;   // 0..131071
    int d = idx >> 8, a = idx & 255;
    g_WT[a * D_ + d] = __float2half_rn(W[d * A_ + a]);
}

// ---------------------------------------------------------------------------
// Kernel A: mma.sync fp16 GEMM on COMPACTED rows. grid (B_, 16).
// CTA (b, t) handles compacted rows [128t, 128t+128) of batch b; early exit.
// Streams fp16(x) of active rows to g_xh (compacted layout).
// Epilogue: e = exp(tanh-dot), store compacted + atomic esum. No softmax pass.
// ---------------------------------------------------------------------------
#define TKC 32
#define NCHUNK (D_ / TKC)           // 16
#define XROW 80                     // 32 fp16 = 64B, padded to 80
#define XBUF (128 * XROW)                   // 10240 per stage
#define OFF_XH 0                            // [2 stages]
#define OFF_W  (2 * XBUF)                   // 20480, [2 stages]
#define WSTAGE (256 * XROW)                 // 20480 per stage
#define OFF_RED (OFF_W + 2 * WSTAGE)        // 61440  (128 floats)
#define OFF_IDX (OFF_RED + 512)             // 61952  (128 ints)
#define OFF_PART (OFF_IDX + 512)            // 62464  (4 floats)
#define SMEM_BYTES (OFF_PART + 16)          // 62480

__global__ __launch_bounds__(512, 1) void logits_mma_kernel(
    const float* __restrict__ x, const float* __restrict__ bias,
    const float* __restrict__ u)
{
    extern __shared__ char smem[];
    const uint32_t sb = smem_u32(smem);
    float* sm_red  = (float*)(smem + OFF_RED);
    int*   sm_idx  = (int*)(smem + OFF_IDX);
    float* sm_part = (float*)(smem + OFF_PART);

    const int b    = blockIdx.x;
    const int jb   = blockIdx.y * 128;        // compacted row base
    const int cnt  = g_cnt[b];
    if (jb >= cnt) return;

    const int tid  = threadIdx.x;
    const int wid  = tid >> 5;
    const int lane = tid & 31;
    const int warp_m = wid & 3;
    const int warp_n = wid >> 2;

    if (tid < 128) {
        sm_red[tid] = 0.f;
        int j = jb + tid;
        sm_idx[tid] = g_idx[b * S_ + (j < cnt ? j : cnt - 1)];
    }
    __syncthreads();

    // x staging mapping: 4 threads per row, 8 floats each (gathered row)
    const int row_x = tid >> 2;
    const int kq_x  = (tid & 3) * 8;
    const float* gx = x + ((size_t)b * S_ + sm_idx[row_x]) * D_ + kq_x;
    __half* gxh_out = g_xh + ((size_t)b * S_ + jb + row_x) * D_ + kq_x;
    const uint32_t xoff = (uint32_t)(row_x * XROW + kq_x * 2);

    // W cp.async mapping: 2 threads per row (n), 2x16B each
    const int n_w  = tid >> 1;
    const int half = tid & 1;
    const __half* gw = g_WT + n_w * D_ + half * 16;
    const uint32_t wdst_row = n_w * XROW + half * 32;

    float acc[2][8][4];
#pragma unroll
    for (int i = 0; i < 2; i++)
#pragma unroll
        for (int j = 0; j < 8; j++)
#pragma unroll
            for (int k = 0; k < 4; k++) acc[i][j][k] = 0.f;

    // ---- preload chunk 0 ----
    {
        float4 v0 = *(const float4*)(gx);
        float4 v1 = *(const float4*)(gx + 4);
        uint4 hi;
        hi.x = pack_h2(v0.x, v0.y); hi.y = pack_h2(v0.z, v0.w);
        hi.z = pack_h2(v1.x, v1.y); hi.w = pack_h2(v1.z, v1.w);
        *(uint4*)(smem + OFF_XH + xoff) = hi;
        *(uint4*)(gxh_out) = hi;

        uint32_t wb = sb + OFF_W;
        cp16(wb + wdst_row,      gw);
        cp16(wb + wdst_row + 16, gw + 8);
        cp_commit();
    }

    // ldmatrix lane addressing
    const int a_row  = (lane & 15);
    const int a_kb   = (lane >> 4) * 16;
    const int t      = lane >> 3;
    const int b_noff = (lane & 7) + 8 * (t >> 1);
    const int b_kb   = 16 * (t & 1);

    for (int c = 0; c < NCHUNK; c++) {
        const int st  = c & 1;
        const int stn = (c + 1) & 1;

        cp_wait0();
        __syncthreads();

        if (c + 1 < NCHUNK) {
            uint32_t wb = sb + OFF_W + stn * WSTAGE;
            const __half* sh = gw + (c + 1) * TKC;
            cp16(wb + wdst_row,      sh);
            cp16(wb + wdst_row + 16, sh + 8);
            cp_commit();
        }
        float4 xv0, xv1;
        if (c + 1 < NCHUNK) {
            xv0 = *(const float4*)(gx + (c + 1) * TKC);
            xv1 = *(const float4*)(gx + (c + 1) * TKC + 4);
        }

        const uint32_t xh = sb + OFF_XH + st * XBUF;
        const uint32_t wh = sb + OFF_W + st * WSTAGE;

#pragma unroll
        for (int ks = 0; ks < 2; ks++) {
            uint32_t ah[2][4];
#pragma unroll
            for (int mt = 0; mt < 2; mt++) {
                uint32_t ra = (warp_m * 32 + mt * 16 + a_row) * XROW + ks * 32 + a_kb;
                ldsm_x4(xh + ra, ah[mt][0], ah[mt][1], ah[mt][2], ah[mt][3]);
            }
#pragma unroll
            for (int pair = 0; pair < 4; pair++) {
                uint32_t rb = (warp_n * 64 + pair * 16 + b_noff) * XROW + ks * 32 + b_kb;
                uint32_t bh0, bh1, bh2, bh3;
                ldsm_x4(wh + rb, bh0, bh1, bh2, bh3);
#pragma unroll
                for (int mt = 0; mt < 2; mt++) {
                    mma_f16(acc[mt][pair * 2 + 0], ah[mt], bh0, bh1);
                    mma_f16(acc[mt][pair * 2 + 1], ah[mt], bh2, bh3);
                }
            }
        }

        if (c + 1 < NCHUNK) {
            uint4 hi;
            hi.x = pack_h2(xv0.x, xv0.y); hi.y = pack_h2(xv0.z, xv0.w);
            hi.z = pack_h2(xv1.x, xv1.y); hi.w = pack_h2(xv1.z, xv1.w);
            *(uint4*)(smem + OFF_XH + stn * XBUF + xoff) = hi;
            *(uint4*)(gxh_out + (c + 1) * TKC) = hi;
        }
    }

    // ---- epilogue: tanh(acc + bias) * u, reduce over 256 cols per row ----
#pragma unroll
    for (int mt = 0; mt < 2; mt++) {
        float r0acc = 0.f, r1acc = 0.f;
#pragma unroll
        for (int j = 0; j < 8; j++) {
            int col = warp_n * 64 + j * 8 + 2 * (lane & 3);
            float b0 = bias[col], b1 = bias[col + 1];
            float u0 = u[col],    u1 = u[col + 1];
            r0acc += tanh_fast(acc[mt][j][0] + b0) * u0
                   + tanh_fast(acc[mt][j][1] + b1) * u1;
            r1acc += tanh_fast(acc[mt][j][2] + b0) * u0
                   + tanh_fast(acc[mt][j][3] + b1) * u1;
        }
        r0acc += __shfl_xor_sync(0xffffffffu, r0acc, 1);
        r0acc += __shfl_xor_sync(0xffffffffu, r0acc, 2);
        r1acc += __shfl_xor_sync(0xffffffffu, r1acc, 1);
        r1acc += __shfl_xor_sync(0xffffffffu, r1acc, 2);
        if ((lane & 3) == 0) {
            int lrow = warp_m * 32 + mt * 16 + (lane >> 2);
            atomicAdd(&sm_red[lrow],     r0acc);
            atomicAdd(&sm_red[lrow + 8], r1acc);
        }
    }
    __syncthreads();

    // exp + compacted store + per-batch sum
    if (tid < 128) {
        int j = jb + tid;
        float e = 0.f;
        if (j < cnt) {
            e = expf(sm_red[tid]);
            g_ewts[b * S_ + j] = e;
        }
        float v = e;
#pragma unroll
        for (int off = 16; off > 0; off >>= 1)
            v += __shfl_xor_sync(0xffffffffu, v, off);
        if (lane == 0) sm_part[wid] = v;
    }
    __syncthreads();
    if (tid == 0)
        atomicAdd(&g_esum[b], sm_part[0] + sm_part[1] + sm_part[2] + sm_part[3]);
}

// ---------------------------------------------------------------------------
// Kernel C: out[b,d] += (1/(esum+EPS)) * sum_j e_j * xh_j[d]  over compacted j
// grid (B_, 8) x 256 compacted rows per block; early exit past cnt.
// ---------------------------------------------------------------------------
#define SCHUNK 256
__global__ __launch_bounds__(512) void wsum_kernel(float* __restrict__ out)
{
    const int b = blockIdx.x;
    const int cnt = g_cnt[b];
    const int j0 = blockIdx.y * SCHUNK;
    if (j0 >= cnt) return;
    const int lim = min(SCHUNK, cnt - j0);

    const int g = threadIdx.x >> 6;          // 0..7
    const int d8 = (threadIdx.x & 63) * 8;   // column group

    __shared__ float wsh[SCHUNK];
    for (int i = threadIdx.x; i < SCHUNK; i += 512)
        wsh[i] = (j0 + i < cnt) ? g_ewts[b * S_ + j0 + i] : 0.f;
    __syncthreads();

    float acc[8];
#pragma unroll
    for (int i = 0; i < 8; i++) acc[i] = 0.f;

    const __half* xp = g_xh + ((size_t)b * S_ + j0) * D_ + d8;
#pragma unroll 8
    for (int s = g; s < lim; s += 8) {
        uint4 v = *(const uint4*)(xp + (size_t)s * D_);
        float w = wsh[s];
        float2 f0 = __half22float2(*(__half2*)&v.x);
        float2 f1 = __half22float2(*(__half2*)&v.y);
        float2 f2 = __half22float2(*(__half2*)&v.z);
        float2 f3 = __half22float2(*(__half2*)&v.w);
        acc[0] = fmaf(f0.x, w, acc[0]); acc[1] = fmaf(f0.y, w, acc[1]);
        acc[2] = fmaf(f1.x, w, acc[2]); acc[3] = fmaf(f1.y, w, acc[3]);
        acc[4] = fmaf(f2.x, w, acc[4]); acc[5] = fmaf(f2.y, w, acc[5]);
        acc[6] = fmaf(f3.x, w, acc[6]); acc[7] = fmaf(f3.y, w, acc[7]);
    }

    const float inv = __fdividef(1.f, g_esum[b] + 1e-7f);
#pragma unroll
    for (int i = 0; i < 8; i++)
        atomicAdd(&out[b * D_ + d8 + i], acc[i] * inv);
}

// ---------------------------------------------------------------------------
extern "C" void kernel_launch(void* const* d_in, const int* in_sizes, int n_in,
                              void* d_out, int out_size)
{
    const float* x    = (const float*)d_in[0];
    const int*   mask = (const int*)d_in[1];
    const float* W    = (const float*)d_in[2];
    const float* bias = (const float*)d_in[3];
    const float* u    = (const float*)d_in[4];
    float*       out  = (float*)d_out;

    cudaFuncSetAttribute(logits_mma_kernel,
                         cudaFuncAttributeMaxDynamicSharedMemorySize, SMEM_BYTES);

    compact_kernel<<<B_, 256>>>(mask, out);
    wprep_kernel<<<512, 256>>>(W);
    logits_mma_kernel<<<dim3(B_, 16), 512, SMEM_BYTES>>>(x, bias, u);
    wsum_kernel<<<dim3(B_, 8), 512>>>(out);
}

// round 10
// speedup vs baseline: 8.4703x; 1.1044x over previous
#include <cuda_runtime.h>
#include <cuda_fp16.h>
#include <math.h>
#include <stdint.h>

#define B_ 64
#define S_ 2048
#define D_ 512
#define A_ 256
#define BS_ (B_ * S_)

// Scratch (allocation-free rule: __device__ globals)
__device__ int    g_idx[BS_];             // per-batch compacted active s indices
__device__ int    g_cnt[B_];              // active count per batch
__device__ float  g_esum[B_];             // per-batch sum of exp(logit)
__device__ float  g_outacc[B_ * D_];      // unnormalized weighted sum
__device__ __half g_WT[A_ * D_];          // W^T fp16 (col-major B for mma)
__device__ __half g_xh[(size_t)BS_ * D_]; // compacted fp16 x rows

// ---------------------------------------------------------------------------
// helpers
// ---------------------------------------------------------------------------
__device__ __forceinline__ uint32_t smem_u32(const void* p) {
    uint32_t a;
    asm("{ .reg .u64 t; cvta.to.shared.u64 t, %1; cvt.u32.u64 %0, t; }"
        : "=r"(a) : "l"(p));
    return a;
}

__device__ __forceinline__ void ldsm_x4(uint32_t addr, uint32_t& r0, uint32_t& r1,
                                        uint32_t& r2, uint32_t& r3) {
    asm volatile("ldmatrix.sync.aligned.m8n8.x4.shared.b16 {%0,%1,%2,%3}, [%4];"
                 : "=r"(r0), "=r"(r1), "=r"(r2), "=r"(r3) : "r"(addr));
}

__device__ __forceinline__ void mma_f16(float* d, const uint32_t* a,
                                        uint32_t b0, uint32_t b1) {
    asm volatile(
        "mma.sync.aligned.m16n8k16.row.col.f32.f16.f16.f32 "
        "{%0,%1,%2,%3}, {%4,%5,%6,%7}, {%8,%9}, {%0,%1,%2,%3};"
        : "+f"(d[0]), "+f"(d[1]), "+f"(d[2]), "+f"(d[3])
        : "r"(a[0]), "r"(a[1]), "r"(a[2]), "r"(a[3]), "r"(b0), "r"(b1));
}

__device__ __forceinline__ void cp16(uint32_t saddr, const void* gptr) {
    asm volatile("cp.async.cg.shared.global [%0], [%1], 16;"
                 :: "r"(saddr), "l"(gptr));
}
__device__ __forceinline__ void cp_commit() {
    asm volatile("cp.async.commit_group;" ::: "memory");
}
__device__ __forceinline__ void cp_wait0() {
    asm volatile("cp.async.wait_group 0;" ::: "memory");
}

__device__ __forceinline__ uint32_t pack_h2(float a, float b) {
    __half2 h = __floats2half2_rn(a, b);
    return *(uint32_t*)&h;
}

// tanh via ex2/rcp MUFU path: err ~1e-6
__device__ __forceinline__ float tanh_fast(float x) {
    float e = __expf(2.f * x);
    return 1.f - __fdividef(2.f, e + 1.f);
}

// ---------------------------------------------------------------------------
// Kernel 0: per-batch mask compaction + W transpose/convert + zero accum.
// grid B_, 256 threads.
// ---------------------------------------------------------------------------
__global__ __launch_bounds__(256) void compact_kernel(
    const int* __restrict__ mask, const float* __restrict__ W)
{
    const int b = blockIdx.x;
    const int tid = threadIdx.x;
    const int lane = tid & 31, w = tid >> 5;
    __shared__ int wbase[8];

    g_outacc[b * 512 + tid] = 0.f;
    g_outacc[b * 512 + 256 + tid] = 0.f;
    if (tid == 0) g_esum[b] = 0.f;

    // W prep slice: this block handles idx range [b*2048, b*2048+2048)
    {
        int base = b * 2048 + tid * 8;   // 8 consecutive idx = same d row
        int d = base >> 8, a0 = base & 255;
#pragma unroll
        for (int i = 0; i < 8; i++) {
            float wv = W[d * A_ + a0 + i];
            g_WT[(a0 + i) * D_ + d] = __float2half_rn(wv);
        }
    }

    int loc[8];
    int c = 0;
    const int* mp = mask + b * S_ + tid * 8;
#pragma unroll
    for (int i = 0; i < 8; i++)
        if (mp[i] != 0) loc[c++] = tid * 8 + i;

    int inc = c;
#pragma unroll
    for (int off = 1; off < 32; off <<= 1) {
        int n = __shfl_up_sync(0xffffffffu, inc, off);
        if (lane >= off) inc += n;
    }
    if (lane == 31) wbase[w] = inc;
    __syncthreads();
    if (tid == 0) {
        int r = 0;
#pragma unroll
        for (int i = 0; i < 8; i++) { int t = wbase[i]; wbase[i] = r; r += t; }
        g_cnt[b] = r;
    }
    __syncthreads();
    int base = wbase[w] + inc - c;
    for (int i = 0; i < c; i++)
        g_idx[b * S_ + base + i] = loc[i];
}

// ---------------------------------------------------------------------------
// Kernel A: mma.sync fp16 GEMM on COMPACTED rows + FUSED weighted sum.
// grid (B_, 16): CTA (b,t) = compacted rows [128t, 128t+128); early exit.
// Mainloop: logits GEMM, streams fp16(x) to g_xh.
// Epilogue: e = exp(tanh-dot); then partial out[b,d] = sum_j e_j xh_j[d]
// (re-reads own g_xh rows -> L2 hits), smem-reduced, atomicAdd to g_outacc.
// ---------------------------------------------------------------------------
#define TKC 32
#define NCHUNK (D_ / TKC)           // 16
#define XROW 80                     // 32 fp16 = 64B, padded to 80
#define XBUF (128 * XROW)                   // 10240 per stage
#define OFF_XH 0                            // [2 stages]
#define OFF_W  (2 * XBUF)                   // 20480, [2 stages]
#define WSTAGE (256 * XROW)                 // 20480 per stage
#define OFF_RED (OFF_W + 2 * WSTAGE)        // 61440  float[128] logits
#define OFF_E   (OFF_RED + 512)             // 61952  float[128] e
#define OFF_IDX (OFF_E + 512)               // 62464  int[128]
#define OFF_PART (OFF_IDX + 512)            // 62976  float[4]
#define SMEM_BYTES (OFF_PART + 16)          // 62992
// sm_wsum[8][512] floats reuses bytes [0, 16384) after mainloop

__global__ __launch_bounds__(512, 1) void logits_mma_kernel(
    const float* __restrict__ x, const float* __restrict__ bias,
    const float* __restrict__ u)
{
    extern __shared__ char smem[];
    const uint32_t sb = smem_u32(smem);
    float* sm_red  = (float*)(smem + OFF_RED);
    float* sm_e    = (float*)(smem + OFF_E);
    int*   sm_idx  = (int*)(smem + OFF_IDX);
    float* sm_part = (float*)(smem + OFF_PART);
    float* sm_wsum = (float*)(smem);            // [8][512] after mainloop

    const int b    = blockIdx.x;
    const int jb   = blockIdx.y * 128;
    const int cnt  = g_cnt[b];
    if (jb >= cnt) return;

    const int tid  = threadIdx.x;
    const int wid  = tid >> 5;
    const int lane = tid & 31;
    const int warp_m = wid & 3;
    const int warp_n = wid >> 2;

    if (tid < 128) {
        sm_red[tid] = 0.f;
        int j = jb + tid;
        sm_idx[tid] = g_idx[b * S_ + (j < cnt ? j : cnt - 1)];
    }
    __syncthreads();

    // x staging mapping: 4 threads per row, 8 floats each (gathered row)
    const int row_x = tid >> 2;
    const int kq_x  = (tid & 3) * 8;
    const float* gx = x + ((size_t)b * S_ + sm_idx[row_x]) * D_ + kq_x;
    __half* gxh_out = g_xh + ((size_t)b * S_ + jb + row_x) * D_ + kq_x;
    const uint32_t xoff = (uint32_t)(row_x * XROW + kq_x * 2);

    // W cp.async mapping: 2 threads per row (n), 2x16B each
    const int n_w  = tid >> 1;
    const int half = tid & 1;
    const __half* gw = g_WT + n_w * D_ + half * 16;
    const uint32_t wdst_row = n_w * XROW + half * 32;

    float acc[2][8][4];
#pragma unroll
    for (int i = 0; i < 2; i++)
#pragma unroll
        for (int j = 0; j < 8; j++)
#pragma unroll
            for (int k = 0; k < 4; k++) acc[i][j][k] = 0.f;

    // ---- preload chunk 0 ----
    {
        float4 v0 = *(const float4*)(gx);
        float4 v1 = *(const float4*)(gx + 4);
        uint4 hi;
        hi.x = pack_h2(v0.x, v0.y); hi.y = pack_h2(v0.z, v0.w);
        hi.z = pack_h2(v1.x, v1.y); hi.w = pack_h2(v1.z, v1.w);
        *(uint4*)(smem + OFF_XH + xoff) = hi;
        *(uint4*)(gxh_out) = hi;

        uint32_t wb = sb + OFF_W;
        cp16(wb + wdst_row,      gw);
        cp16(wb + wdst_row + 16, gw + 8);
        cp_commit();
    }

    // ldmatrix lane addressing
    const int a_row  = (lane & 15);
    const int a_kb   = (lane >> 4) * 16;
    const int t      = lane >> 3;
    const int b_noff = (lane & 7) + 8 * (t >> 1);
    const int b_kb   = 16 * (t & 1);

    for (int c = 0; c < NCHUNK; c++) {
        const int st  = c & 1;
        const int stn = (c + 1) & 1;

        cp_wait0();
        __syncthreads();

        if (c + 1 < NCHUNK) {
            uint32_t wb = sb + OFF_W + stn * WSTAGE;
            const __half* sh = gw + (c + 1) * TKC;
            cp16(wb + wdst_row,      sh);
            cp16(wb + wdst_row + 16, sh + 8);
            cp_commit();
        }
        float4 xv0, xv1;
        if (c + 1 < NCHUNK) {
            xv0 = *(const float4*)(gx + (c + 1) * TKC);
            xv1 = *(const float4*)(gx + (c + 1) * TKC + 4);
        }

        const uint32_t xh = sb + OFF_XH + st * XBUF;
        const uint32_t wh = sb + OFF_W + st * WSTAGE;

#pragma unroll
        for (int ks = 0; ks < 2; ks++) {
            uint32_t ah[2][4];
#pragma unroll
            for (int mt = 0; mt < 2; mt++) {
                uint32_t ra = (warp_m * 32 + mt * 16 + a_row) * XROW + ks * 32 + a_kb;
                ldsm_x4(xh + ra, ah[mt][0], ah[mt][1], ah[mt][2], ah[mt][3]);
            }
#pragma unroll
            for (int pair = 0; pair < 4; pair++) {
                uint32_t rb = (warp_n * 64 + pair * 16 + b_noff) * XROW + ks * 32 + b_kb;
                uint32_t bh0, bh1, bh2, bh3;
                ldsm_x4(wh + rb, bh0, bh1, bh2, bh3);
#pragma unroll
                for (int mt = 0; mt < 2; mt++) {
                    mma_f16(acc[mt][pair * 2 + 0], ah[mt], bh0, bh1);
                    mma_f16(acc[mt][pair * 2 + 1], ah[mt], bh2, bh3);
                }
            }
        }

        if (c + 1 < NCHUNK) {
            uint4 hi;
            hi.x = pack_h2(xv0.x, xv0.y); hi.y = pack_h2(xv0.z, xv0.w);
            hi.z = pack_h2(xv1.x, xv1.y); hi.w = pack_h2(xv1.z, xv1.w);
            *(uint4*)(smem + OFF_XH + stn * XBUF + xoff) = hi;
            *(uint4*)(gxh_out + (c + 1) * TKC) = hi;
        }
    }

    // ---- epilogue 1: tanh(acc + bias) * u, reduce over 256 cols per row ----
#pragma unroll
    for (int mt = 0; mt < 2; mt++) {
        float r0acc = 0.f, r1acc = 0.f;
#pragma unroll
        for (int j = 0; j < 8; j++) {
            int col = warp_n * 64 + j * 8 + 2 * (lane & 3);
            float b0 = bias[col], b1 = bias[col + 1];
            float u0 = u[col],    u1 = u[col + 1];
            r0acc += tanh_fast(acc[mt][j][0] + b0) * u0
                   + tanh_fast(acc[mt][j][1] + b1) * u1;
            r1acc += tanh_fast(acc[mt][j][2] + b0) * u0
                   + tanh_fast(acc[mt][j][3] + b1) * u1;
        }
        r0acc += __shfl_xor_sync(0xffffffffu, r0acc, 1);
        r0acc += __shfl_xor_sync(0xffffffffu, r0acc, 2);
        r1acc += __shfl_xor_sync(0xffffffffu, r1acc, 1);
        r1acc += __shfl_xor_sync(0xffffffffu, r1acc, 2);
        if ((lane & 3) == 0) {
            int lrow = warp_m * 32 + mt * 16 + (lane >> 2);
            atomicAdd(&sm_red[lrow],     r0acc);
            atomicAdd(&sm_red[lrow + 8], r1acc);
        }
    }
    __syncthreads();

    // ---- epilogue 2: e = exp(logit) (0 past cnt), esum partial ----
    if (tid < 128) {
        int j = jb + tid;
        float e = (j < cnt) ? expf(sm_red[tid]) : 0.f;
        sm_e[tid] = e;
        float v = e;
#pragma unroll
        for (int off = 16; off > 0; off >>= 1)
            v += __shfl_xor_sync(0xffffffffu, v, off);
        if (lane == 0) sm_part[wid] = v;
    }
    __syncthreads();
    if (tid == 0)
        atomicAdd(&g_esum[b], sm_part[0] + sm_part[1] + sm_part[2] + sm_part[3]);

    // ---- epilogue 3: fused weighted sum over this tile's 128 rows ----
    // thread layout: 8 row-groups x 64 threads; 8 cols (uint4) per thread.
    {
        const int g  = tid >> 6;               // 0..7
        const int d8 = (tid & 63) * 8;
        float a8[8];
#pragma unroll
        for (int i = 0; i < 8; i++) a8[i] = 0.f;

        const __half* xb = g_xh + ((size_t)b * S_ + jb) * D_ + d8;
#pragma unroll 4
        for (int j = g; j < 128; j += 8) {     // L2 hits: self-written rows
            uint4 v = *(const uint4*)(xb + (size_t)j * D_);
            float w = sm_e[j];
            float2 f0 = __half22float2(*(__half2*)&v.x);
            float2 f1 = __half22float2(*(__half2*)&v.y);
            float2 f2 = __half22float2(*(__half2*)&v.z);
            float2 f3 = __half22float2(*(__half2*)&v.w);
            a8[0] = fmaf(f0.x, w, a8[0]); a8[1] = fmaf(f0.y, w, a8[1]);
            a8[2] = fmaf(f1.x, w, a8[2]); a8[3] = fmaf(f1.y, w, a8[3]);
            a8[4] = fmaf(f2.x, w, a8[4]); a8[5] = fmaf(f2.y, w, a8[5]);
            a8[6] = fmaf(f3.x, w, a8[6]); a8[7] = fmaf(f3.y, w, a8[7]);
        }
        // conflict-free staging: sm_wsum[g][d8..d8+7]
        *(float4*)(&sm_wsum[g * 512 + d8])     = make_float4(a8[0], a8[1], a8[2], a8[3]);
        *(float4*)(&sm_wsum[g * 512 + d8 + 4]) = make_float4(a8[4], a8[5], a8[6], a8[7]);
    }
    __syncthreads();
    {
        float s = 0.f;
#pragma unroll
        for (int g = 0; g < 8; g++) s += sm_wsum[g * 512 + tid];
        atomicAdd(&g_outacc[b * 512 + tid], s);
    }
}

// ---------------------------------------------------------------------------
// Kernel S: out[b,d] = g_outacc[b,d] / (esum[b] + EPS)
// ---------------------------------------------------------------------------
__global__ __launch_bounds__(512) void scale_kernel(float* __restrict__ out)
{
    const int b = blockIdx.x;
    const float inv = __fdividef(1.f, g_esum[b] + 1e-7f);
    out[b * 512 + threadIdx.x] = g_outacc[b * 512 + threadIdx.x] * inv;
}

// ---------------------------------------------------------------------------
extern "C" void kernel_launch(void* const* d_in, const int* in_sizes, int n_in,
                              void* d_out, int out_size)
{
    const float* x    = (const float*)d_in[0];
    const int*   mask = (const int*)d_in[1];
    const float* W    = (const float*)d_in[2];
    const float* bias = (const float*)d_in[3];
    const float* u    = (const float*)d_in[4];
    float*       out  = (float*)d_out;

    cudaFuncSetAttribute(logits_mma_kernel,
                         cudaFuncAttributeMaxDynamicSharedMemorySize, SMEM_BYTES);

    compact_kernel<<<B_, 256>>>(mask, W);
    logits_mma_kernel<<<dim3(B_, 16), 512, SMEM_BYTES>>>(x, bias, u);
    scale_kernel<<<B_, 512>>>(out);
}

// round 11
// speedup vs baseline: 8.9987x; 1.0624x over previous
#include <cuda_runtime.h>
#include <cuda_fp16.h>
#include <math.h>
#include <stdint.h>

#define B_ 64
#define S_ 2048
#define D_ 512
#define A_ 256
#define BS_ (B_ * S_)

// Scratch (allocation-free rule: __device__ globals)
__device__ int    g_idx[BS_];             // per-batch compacted active s indices
__device__ int    g_cnt[B_];              // active count per batch
__device__ float  g_esum[B_];             // per-batch sum of exp(logit)
__device__ float  g_outacc[B_ * D_];      // unnormalized weighted sum
__device__ __half g_WT[A_ * D_];          // W^T fp16 (col-major B for mma)

// ---------------------------------------------------------------------------
// helpers
// ---------------------------------------------------------------------------
__device__ __forceinline__ uint32_t smem_u32(const void* p) {
    uint32_t a;
    asm("{ .reg .u64 t; cvta.to.shared.u64 t, %1; cvt.u32.u64 %0, t; }"
        : "=r"(a) : "l"(p));
    return a;
}

__device__ __forceinline__ void ldsm_x4(uint32_t addr, uint32_t& r0, uint32_t& r1,
                                        uint32_t& r2, uint32_t& r3) {
    asm volatile("ldmatrix.sync.aligned.m8n8.x4.shared.b16 {%0,%1,%2,%3}, [%4];"
                 : "=r"(r0), "=r"(r1), "=r"(r2), "=r"(r3) : "r"(addr));
}

__device__ __forceinline__ void mma_f16(float* d, const uint32_t* a,
                                        uint32_t b0, uint32_t b1) {
    asm volatile(
        "mma.sync.aligned.m16n8k16.row.col.f32.f16.f16.f32 "
        "{%0,%1,%2,%3}, {%4,%5,%6,%7}, {%8,%9}, {%0,%1,%2,%3};"
        : "+f"(d[0]), "+f"(d[1]), "+f"(d[2]), "+f"(d[3])
        : "r"(a[0]), "r"(a[1]), "r"(a[2]), "r"(a[3]), "r"(b0), "r"(b1));
}

__device__ __forceinline__ void cp16(uint32_t saddr, const void* gptr) {
    asm volatile("cp.async.cg.shared.global [%0], [%1], 16;"
                 :: "r"(saddr), "l"(gptr));
}
__device__ __forceinline__ void cp_commit() {
    asm volatile("cp.async.commit_group;" ::: "memory");
}
__device__ __forceinline__ void cp_wait0() {
    asm volatile("cp.async.wait_group 0;" ::: "memory");
}

__device__ __forceinline__ uint32_t pack_h2(float a, float b) {
    __half2 h = __floats2half2_rn(a, b);
    return *(uint32_t*)&h;
}

// tanh via ex2/rcp MUFU path: err ~1e-6
__device__ __forceinline__ float tanh_fast(float x) {
    float e = __expf(2.f * x);
    return 1.f - __fdividef(2.f, e + 1.f);
}

// ---------------------------------------------------------------------------
// Kernel 0: per-batch mask compaction + W transpose/convert + zero accum.
// grid B_, 1024 threads: 2 mask elems + 2 W elems per thread.
// ---------------------------------------------------------------------------
__global__ __launch_bounds__(1024) void compact_kernel(
    const int* __restrict__ mask, const float* __restrict__ W)
{
    const int b = blockIdx.x;
    const int tid = threadIdx.x;
    const int lane = tid & 31, w = tid >> 5;
    __shared__ int wbase[32];

    if (tid < 512) g_outacc[b * 512 + tid] = 0.f;
    if (tid == 0) g_esum[b] = 0.f;

    // W prep slice: block b handles idx [b*2048, b*2048+2048), 2 per thread
    {
        int base = b * 2048 + tid * 2;
        int d = base >> 8, a0 = base & 255;
        g_WT[(a0 + 0) * D_ + d] = __float2half_rn(W[d * A_ + a0 + 0]);
        g_WT[(a0 + 1) * D_ + d] = __float2half_rn(W[d * A_ + a0 + 1]);
    }

    // mask: thread handles s = tid*2, tid*2+1
    int m0 = mask[b * S_ + tid * 2];
    int m1 = mask[b * S_ + tid * 2 + 1];
    int c = (m0 != 0) + (m1 != 0);

    int inc = c;
#pragma unroll
    for (int off = 1; off < 32; off <<= 1) {
        int n = __shfl_up_sync(0xffffffffu, inc, off);
        if (lane >= off) inc += n;
    }
    if (lane == 31) wbase[w] = inc;
    __syncthreads();
    if (tid == 0) {
        int r = 0;
#pragma unroll
        for (int i = 0; i < 32; i++) { int t = wbase[i]; wbase[i] = r; r += t; }
        g_cnt[b] = r;
    }
    __syncthreads();
    int base = wbase[w] + inc - c;
    if (m0 != 0) g_idx[b * S_ + base++] = tid * 2;
    if (m1 != 0) g_idx[b * S_ + base]   = tid * 2 + 1;
}

// ---------------------------------------------------------------------------
// Kernel A: mma.sync fp16 GEMM on COMPACTED rows + fully SMEM-fused wsum.
// grid (B_, 16): CTA (b,t) = compacted rows [128t, 128t+128); early exit.
// The whole 128x512 fp16 x tile stays in SMEM (row-major, 1040B stride);
// epilogue weighted sum reads SMEM, no global x round-trip at all.
// ---------------------------------------------------------------------------
#define TKC 32
#define NCHUNK (D_ / TKC)           // 16
#define XROW 80                     // staging: 32 fp16 = 64B, padded to 80
#define XBUF (128 * XROW)                   // 10240 per stage
#define FROW 1040                           // full tile row stride (512*2 + 16)
#define OFF_XH 0                            // [2 stages]
#define OFF_W  (2 * XBUF)                   // 20480, [2 stages]
#define WSTAGE (256 * XROW)                 // 20480 per stage
#define OFF_FULL (OFF_W + 2 * WSTAGE)       // 61440, 128*1040 = 133120
#define OFF_RED (OFF_FULL + 128 * FROW)     // 194560 float[128]
#define OFF_E   (OFF_RED + 512)             // 195072 float[128]
#define OFF_IDX (OFF_E + 512)               // 195584 int[128]
#define OFF_PART (OFF_IDX + 512)            // 196096 float[4]
#define SMEM_BYTES (OFF_PART + 16)          // 196112
// sm_wsum[8][512] floats reuses bytes [0, 16384) after mainloop

__global__ __launch_bounds__(512, 1) void logits_mma_kernel(
    const float* __restrict__ x, const float* __restrict__ bias,
    const float* __restrict__ u)
{
    extern __shared__ char smem[];
    const uint32_t sb = smem_u32(smem);
    float* sm_red  = (float*)(smem + OFF_RED);
    float* sm_e    = (float*)(smem + OFF_E);
    int*   sm_idx  = (int*)(smem + OFF_IDX);
    float* sm_part = (float*)(smem + OFF_PART);
    float* sm_wsum = (float*)(smem);            // [8][512] after mainloop

    const int b    = blockIdx.x;
    const int jb   = blockIdx.y * 128;
    const int cnt  = g_cnt[b];
    if (jb >= cnt) return;

    const int tid  = threadIdx.x;
    const int wid  = tid >> 5;
    const int lane = tid & 31;
    const int warp_m = wid & 3;
    const int warp_n = wid >> 2;

    if (tid < 128) {
        sm_red[tid] = 0.f;
        int j = jb + tid;
        sm_idx[tid] = g_idx[b * S_ + (j < cnt ? j : cnt - 1)];
    }
    __syncthreads();

    // x staging mapping: 4 threads per row, 8 floats each (gathered row)
    const int row_x = tid >> 2;
    const int kq_x  = (tid & 3) * 8;
    const float* gx = x + ((size_t)b * S_ + sm_idx[row_x]) * D_ + kq_x;
    const uint32_t xoff = (uint32_t)(row_x * XROW + kq_x * 2);
    char* full_out = smem + OFF_FULL + row_x * FROW + kq_x * 2;

    // W cp.async mapping: 2 threads per row (n), 2x16B each
    const int n_w  = tid >> 1;
    const int half = tid & 1;
    const __half* gw = g_WT + n_w * D_ + half * 16;
    const uint32_t wdst_row = n_w * XROW + half * 32;

    float acc[2][8][4];
#pragma unroll
    for (int i = 0; i < 2; i++)
#pragma unroll
        for (int j = 0; j < 8; j++)
#pragma unroll
            for (int k = 0; k < 4; k++) acc[i][j][k] = 0.f;

    // ---- preload chunk 0 ----
    {
        float4 v0 = *(const float4*)(gx);
        float4 v1 = *(const float4*)(gx + 4);
        uint4 hi;
        hi.x = pack_h2(v0.x, v0.y); hi.y = pack_h2(v0.z, v0.w);
        hi.z = pack_h2(v1.x, v1.y); hi.w = pack_h2(v1.z, v1.w);
        *(uint4*)(smem + OFF_XH + xoff) = hi;
        *(uint4*)(full_out) = hi;

        uint32_t wb = sb + OFF_W;
        cp16(wb + wdst_row,      gw);
        cp16(wb + wdst_row + 16, gw + 8);
        cp_commit();
    }

    // ldmatrix lane addressing
    const int a_row  = (lane & 15);
    const int a_kb   = (lane >> 4) * 16;
    const int t      = lane >> 3;
    const int b_noff = (lane & 7) + 8 * (t >> 1);
    const int b_kb   = 16 * (t & 1);

    for (int c = 0; c < NCHUNK; c++) {
        const int st  = c & 1;
        const int stn = (c + 1) & 1;

        cp_wait0();
        __syncthreads();

        if (c + 1 < NCHUNK) {
            uint32_t wb = sb + OFF_W + stn * WSTAGE;
            const __half* sh = gw + (c + 1) * TKC;
            cp16(wb + wdst_row,      sh);
            cp16(wb + wdst_row + 16, sh + 8);
            cp_commit();
        }
        float4 xv0, xv1;
        if (c + 1 < NCHUNK) {
            xv0 = *(const float4*)(gx + (c + 1) * TKC);
            xv1 = *(const float4*)(gx + (c + 1) * TKC + 4);
        }

        const uint32_t xh = sb + OFF_XH + st * XBUF;
        const uint32_t wh = sb + OFF_W + st * WSTAGE;

#pragma unroll
        for (int ks = 0; ks < 2; ks++) {
            uint32_t ah[2][4];
#pragma unroll
            for (int mt = 0; mt < 2; mt++) {
                uint32_t ra = (warp_m * 32 + mt * 16 + a_row) * XROW + ks * 32 + a_kb;
                ldsm_x4(xh + ra, ah[mt][0], ah[mt][1], ah[mt][2], ah[mt][3]);
            }
#pragma unroll
            for (int pair = 0; pair < 4; pair++) {
                uint32_t rb = (warp_n * 64 + pair * 16 + b_noff) * XROW + ks * 32 + b_kb;
                uint32_t bh0, bh1, bh2, bh3;
                ldsm_x4(wh + rb, bh0, bh1, bh2, bh3);
#pragma unroll
                for (int mt = 0; mt < 2; mt++) {
                    mma_f16(acc[mt][pair * 2 + 0], ah[mt], bh0, bh1);
                    mma_f16(acc[mt][pair * 2 + 1], ah[mt], bh2, bh3);
                }
            }
        }

        if (c + 1 < NCHUNK) {
            uint4 hi;
            hi.x = pack_h2(xv0.x, xv0.y); hi.y = pack_h2(xv0.z, xv0.w);
            hi.z = pack_h2(xv1.x, xv1.y); hi.w = pack_h2(xv1.z, xv1.w);
            *(uint4*)(smem + OFF_XH + stn * XBUF + xoff) = hi;
            *(uint4*)(full_out + (c + 1) * (TKC * 2)) = hi;
        }
    }

    // ---- epilogue 1: tanh(acc + bias) * u, reduce over 256 cols per row ----
#pragma unroll
    for (int mt = 0; mt < 2; mt++) {
        float r0acc = 0.f, r1acc = 0.f;
#pragma unroll
        for (int j = 0; j < 8; j++) {
            int col = warp_n * 64 + j * 8 + 2 * (lane & 3);
            float b0 = bias[col], b1 = bias[col + 1];
            float u0 = u[col],    u1 = u[col + 1];
            r0acc += tanh_fast(acc[mt][j][0] + b0) * u0
                   + tanh_fast(acc[mt][j][1] + b1) * u1;
            r1acc += tanh_fast(acc[mt][j][2] + b0) * u0
                   + tanh_fast(acc[mt][j][3] + b1) * u1;
        }
        r0acc += __shfl_xor_sync(0xffffffffu, r0acc, 1);
        r0acc += __shfl_xor_sync(0xffffffffu, r0acc, 2);
        r1acc += __shfl_xor_sync(0xffffffffu, r1acc, 1);
        r1acc += __shfl_xor_sync(0xffffffffu, r1acc, 2);
        if ((lane & 3) == 0) {
            int lrow = warp_m * 32 + mt * 16 + (lane >> 2);
            atomicAdd(&sm_red[lrow],     r0acc);
            atomicAdd(&sm_red[lrow + 8], r1acc);
        }
    }
    __syncthreads();

    // ---- epilogue 2: e = exp(logit) (0 past cnt), esum partial ----
    if (tid < 128) {
        int j = jb + tid;
        float e = (j < cnt) ? expf(sm_red[tid]) : 0.f;
        sm_e[tid] = e;
        float v = e;
#pragma unroll
        for (int off = 16; off > 0; off >>= 1)
            v += __shfl_xor_sync(0xffffffffu, v, off);
        if (lane == 0) sm_part[wid] = v;
    }
    __syncthreads();
    if (tid == 0)
        atomicAdd(&g_esum[b], sm_part[0] + sm_part[1] + sm_part[2] + sm_part[3]);

    // ---- epilogue 3: fused weighted sum, all reads from SMEM full tile ----
    // 8 row-groups x 64 threads; 8 cols (uint4) per thread; rows j=g,g+8,...
    {
        const int g  = tid >> 6;               // 0..7
        const int d8 = (tid & 63) * 8;
        float a8[8];
#pragma unroll
        for (int i = 0; i < 8; i++) a8[i] = 0.f;

        const char* xb = smem + OFF_FULL + d8 * 2;
#pragma unroll 4
        for (int j = g; j < 128; j += 8) {
            uint4 v = *(const uint4*)(xb + j * FROW);
            float w = sm_e[j];
            float2 f0 = __half22float2(*(__half2*)&v.x);
            float2 f1 = __half22float2(*(__half2*)&v.y);
            float2 f2 = __half22float2(*(__half2*)&v.z);
            float2 f3 = __half22float2(*(__half2*)&v.w);
            a8[0] = fmaf(f0.x, w, a8[0]); a8[1] = fmaf(f0.y, w, a8[1]);
            a8[2] = fmaf(f1.x, w, a8[2]); a8[3] = fmaf(f1.y, w, a8[3]);
            a8[4] = fmaf(f2.x, w, a8[4]); a8[5] = fmaf(f2.y, w, a8[5]);
            a8[6] = fmaf(f3.x, w, a8[6]); a8[7] = fmaf(f3.y, w, a8[7]);
        }
        __syncthreads();   // mainloop smem (stage region) now reusable
        *(float4*)(&sm_wsum[g * 512 + d8])     = make_float4(a8[0], a8[1], a8[2], a8[3]);
        *(float4*)(&sm_wsum[g * 512 + d8 + 4]) = make_float4(a8[4], a8[5], a8[6], a8[7]);
    }
    __syncthreads();
    {
        float s = 0.f;
#pragma unroll
        for (int g = 0; g < 8; g++) s += sm_wsum[g * 512 + tid];
        atomicAdd(&g_outacc[b * 512 + tid], s);
    }
}

// ---------------------------------------------------------------------------
// Kernel S: out[b,d] = g_outacc[b,d] / (esum[b] + EPS)
// ---------------------------------------------------------------------------
__global__ __launch_bounds__(512) void scale_kernel(float* __restrict__ out)
{
    const int b = blockIdx.x;
    const float inv = __fdividef(1.f, g_esum[b] + 1e-7f);
    out[b * 512 + threadIdx.x] = g_outacc[b * 512 + threadIdx.x] * inv;
}

// ---------------------------------------------------------------------------
extern "C" void kernel_launch(void* const* d_in, const int* in_sizes, int n_in,
                              void* d_out, int out_size)
{
    const float* x    = (const float*)d_in[0];
    const int*   mask = (const int*)d_in[1];
    const float* W    = (const float*)d_in[2];
    const float* bias = (const float*)d_in[3];
    const float* u    = (const float*)d_in[4];
    float*       out  = (float*)d_out;

    cudaFuncSetAttribute(logits_mma_kernel,
                         cudaFuncAttributeMaxDynamicSharedMemorySize, SMEM_BYTES);

    compact_kernel<<<B_, 1024>>>(mask, W);
    logits_mma_kernel<<<dim3(B_, 16), 512, SMEM_BYTES>>>(x, bias, u);
    scale_kernel<<<B_, 512>>>(out);
}